// round 7
// baseline (speedup 1.0000x reference)
#include <cuda_runtime.h>

#define NN 20000
#define NE 10000
#define IC 128
#define OC 64
#define SPLIT1 8
#define SPLIT2 4
#define CHUNK1 2528   // 79 k-tiles of 32
#define CHUNK2 2528

// Scratch (device globals — no allocation in kernel_launch).
__device__ float g_xwT_hi[OC * NN];          // tf32(xw)^T        [64][20000]
__device__ float g_xwT_lo[OC * NN];          // tf32(xw-hi)^T     [64][20000]
__device__ float g_ef[NE * OC];              // edge features     [E][64]
__device__ float g_ef_part[SPLIT1 * NE * OC];
__device__ float g_de_part[SPLIT1 * NE];
__device__ float g_out_part[SPLIT2 * NN * OC];
__device__ float g_dn_part[SPLIT2 * NN];

// ---------------------------------------------------------------------------
// helpers
// ---------------------------------------------------------------------------
__device__ __forceinline__ float to_tf32(float x) {
    unsigned u;
    asm("cvt.rna.tf32.f32 %0, %1;" : "=r"(u) : "f"(x));
    return __uint_as_float(u);
}
__device__ __forceinline__ unsigned tf32u(float x) {
    unsigned u;
    asm("cvt.rna.tf32.f32 %0, %1;" : "=r"(u) : "f"(x));
    return u;
}
// mma.m16n8k8 tf32: A row-major [16,8], B col-major [8,8], C fp32 [16,8]
__device__ __forceinline__ void mma8(float* c, unsigned a0, unsigned a1,
                                     unsigned a2, unsigned a3,
                                     unsigned b0, unsigned b1) {
    asm volatile(
        "mma.sync.aligned.m16n8k8.row.col.f32.tf32.tf32.f32 "
        "{%0,%1,%2,%3}, {%4,%5,%6,%7}, {%8,%9}, {%0,%1,%2,%3};\n"
        : "+f"(c[0]), "+f"(c[1]), "+f"(c[2]), "+f"(c[3])
        : "r"(a0), "r"(a1), "r"(a2), "r"(a3), "r"(b0), "r"(b1));
}
// cp.async 16B with zero-fill predicate (src-size 0 reads nothing)
__device__ __forceinline__ void cpa16(float* dst, const float* src, bool pred) {
    unsigned sdst = (unsigned)__cvta_generic_to_shared(dst);
    int sz = pred ? 16 : 0;
    asm volatile("cp.async.cg.shared.global [%0], [%1], 16, %2;\n"
                 :: "r"(sdst), "l"(src), "r"(sz));
}
__device__ __forceinline__ void cpa_commit() {
    asm volatile("cp.async.commit_group;\n");
}
template <int N>
__device__ __forceinline__ void cpa_wait() {
    asm volatile("cp.async.wait_group %0;\n" :: "n"(N));
}

// ---------------------------------------------------------------------------
// Kernel 1: xw = x @ theta, stored TRANSPOSED as tf32 hi/lo pairs.
// ---------------------------------------------------------------------------
__global__ __launch_bounds__(128) void k_xw(const float* __restrict__ x,
                                            const float* __restrict__ theta) {
    __shared__ float a_s[32][33];
    __shared__ float b_s[32][64];
    const int tid = threadIdx.x;
    const int rg  = tid >> 3;
    const int cg  = tid & 7;
    const int n0  = blockIdx.x * 32;

    float acc[2][8];
#pragma unroll
    for (int i = 0; i < 2; i++)
#pragma unroll
        for (int j = 0; j < 8; j++) acc[i][j] = 0.f;

    for (int k0 = 0; k0 < IC; k0 += 32) {
#pragma unroll
        for (int t = 0; t < 8; t++) {
            int idx = tid + t * 128;
            int i = idx >> 5, j = idx & 31;
            a_s[j][i] = x[(n0 + i) * IC + k0 + j];
        }
#pragma unroll
        for (int t = 0; t < 4; t++) {
            int idx4 = tid + t * 128;
            int r = idx4 >> 4, c4 = idx4 & 15;
            ((float4*)b_s[r])[c4] = ((const float4*)(theta + (k0 + r) * OC))[c4];
        }
        __syncthreads();
#pragma unroll
        for (int k = 0; k < 32; k++) {
            float a0 = a_s[k][rg * 2 + 0];
            float a1 = a_s[k][rg * 2 + 1];
            float4 b0 = *(float4*)&b_s[k][cg * 8 + 0];
            float4 b1 = *(float4*)&b_s[k][cg * 8 + 4];
            float bb[8] = {b0.x, b0.y, b0.z, b0.w, b1.x, b1.y, b1.z, b1.w};
#pragma unroll
            for (int j = 0; j < 8; j++) {
                acc[0][j] += a0 * bb[j];
                acc[1][j] += a1 * bb[j];
            }
        }
        __syncthreads();
    }
#pragma unroll
    for (int i = 0; i < 2; i++) {
        int n = n0 + rg * 2 + i;
#pragma unroll
        for (int j = 0; j < 8; j++) {
            int c = cg * 8 + j;
            float v  = acc[i][j];
            float hi = to_tf32(v);
            float lo = to_tf32(v - hi);
            g_xwT_hi[c * NN + n] = hi;
            g_xwT_lo[c * NN + n] = lo;
        }
    }
}

// ---------------------------------------------------------------------------
// Pass 1 (partial): ef^T[c][e] += sum_{n in chunk} xwT[c][n] * H[n][e]
// Tile M(c)=64 x N(e)=128, BK=32. 256 thr / 8 warps (4 M x 2 N).
// Grid (79, SPLIT1). Double-buffered cp.async. Raw H in smem (exact de);
// tf32 rounding applied at fragment-load time.
// ---------------------------------------------------------------------------
__global__ __launch_bounds__(256) void k_edge_p(const float* __restrict__ H) {
    extern __shared__ float sm[];
    float* Ah = sm;                   // [2][64*36]
    float* Al = sm + 2 * 2304;        // [2][64*36]
    float* Bs = sm + 4 * 2304;        // [2][32*136]
    __shared__ float sred[256];

    const int tid  = threadIdx.x;
    const int lane = tid & 31, w = tid >> 5;
    const int g = lane >> 2, q = lane & 3;
    const int wm = w & 3, wn = w >> 2;
    const int e0 = blockIdx.x * 128;
    const int sp = blockIdx.y;
    const int kbeg = sp * CHUNK1;
    const int kend = (kbeg + CHUNK1 < NN) ? (kbeg + CHUNK1) : NN;

    const int arow = tid >> 3;        // 0..31 (+32)
    const int ak4  = (tid & 7) * 4;
    const int brow = tid >> 3;        // 0..31
    const int bc0  = (tid & 7) * 4;

    float acc[8][4];
#pragma unroll
    for (int nt = 0; nt < 8; nt++)
#pragma unroll
        for (int r = 0; r < 4; r++) acc[nt][r] = 0.f;
    float de_acc = 0.f;

    auto load = [&](int buf, int k0) {
#pragma unroll
        for (int i = 0; i < 2; i++) {
            int r = arow + 32 * i;
            long go = (long)r * NN + k0 + ak4;
            cpa16(Ah + buf * 2304 + r * 36 + ak4, g_xwT_hi + go, true);
            cpa16(Al + buf * 2304 + r * 36 + ak4, g_xwT_lo + go, true);
        }
        long ho = (long)(k0 + brow) * NE;
#pragma unroll
        for (int j = 0; j < 4; j++) {
            int ec = bc0 + 32 * j;
            cpa16(Bs + buf * 4352 + brow * 136 + ec, H + ho + e0 + ec,
                  (e0 + ec) < NE);
        }
    };

    load(0, kbeg);
    cpa_commit();
    int buf = 0;
    for (int k0 = kbeg; k0 < kend; k0 += 32) {
        bool hn = (k0 + 32) < kend;
        if (hn) { load(buf ^ 1, k0 + 32); cpa_commit(); cpa_wait<1>(); }
        else    { cpa_wait<0>(); }
        __syncthreads();
        const float* ah = Ah + buf * 2304;
        const float* al = Al + buf * 2304;
        const float* bs = Bs + buf * 4352;
        {   // exact fp32 column-sum partial from raw H
            int col = tid >> 1, h = (tid & 1) * 16;
#pragma unroll
            for (int k = 0; k < 16; k++) de_acc += bs[(h + k) * 136 + col];
        }
#pragma unroll
        for (int ks = 0; ks < 32; ks += 8) {
            const int ar = wm * 16;
            unsigned h0 = __float_as_uint(ah[(ar + g) * 36 + ks + q]);
            unsigned h1 = __float_as_uint(ah[(ar + g + 8) * 36 + ks + q]);
            unsigned h2 = __float_as_uint(ah[(ar + g) * 36 + ks + q + 4]);
            unsigned h3 = __float_as_uint(ah[(ar + g + 8) * 36 + ks + q + 4]);
            unsigned l0 = __float_as_uint(al[(ar + g) * 36 + ks + q]);
            unsigned l1 = __float_as_uint(al[(ar + g + 8) * 36 + ks + q]);
            unsigned l2 = __float_as_uint(al[(ar + g) * 36 + ks + q + 4]);
            unsigned l3 = __float_as_uint(al[(ar + g + 8) * 36 + ks + q + 4]);
#pragma unroll
            for (int nt = 0; nt < 8; nt++) {
                unsigned b0 = tf32u(bs[(ks + q) * 136 + wn * 64 + nt * 8 + g]);
                unsigned b1 = tf32u(bs[(ks + q + 4) * 136 + wn * 64 + nt * 8 + g]);
                mma8(acc[nt], h0, h1, h2, h3, b0, b1);
                mma8(acc[nt], l0, l1, l2, l3, b0, b1);
            }
        }
        __syncthreads();
        buf ^= 1;
    }

    sred[tid] = de_acc;
    __syncthreads();
    if (tid < 128) {
        int e = e0 + tid;
        if (e < NE) g_de_part[sp * NE + e] = sred[2 * tid] + sred[2 * tid + 1];
    }

    float* op = g_ef_part + sp * NE * OC;
    const int c0 = wm * 16 + g;
#pragma unroll
    for (int nt = 0; nt < 8; nt++) {
        int eA = e0 + wn * 64 + nt * 8 + 2 * q;
        int eB = eA + 1;
        if (eA < NE) { op[eA * OC + c0] = acc[nt][0]; op[eA * OC + c0 + 8] = acc[nt][2]; }
        if (eB < NE) { op[eB * OC + c0] = acc[nt][1]; op[eB * OC + c0 + 8] = acc[nt][3]; }
    }
}

// Finalize pass 1: ef = (sum_s part) / (sum_s de_part)
__global__ __launch_bounds__(256) void k_fin1() {
    int idx = blockIdx.x * 256 + threadIdx.x;   // e*64 + c, exact cover
    int e = idx >> 6;
    float s = 0.f, d = 0.f;
#pragma unroll
    for (int sp = 0; sp < SPLIT1; sp++) {
        s += g_ef_part[sp * NE * OC + idx];
        d += g_de_part[sp * NE + e];
    }
    g_ef[idx] = s / d;
}

// ---------------------------------------------------------------------------
// Pass 2 (partial): out[n][c] += sum_{e in chunk} H[n][e] * ef[e][c]
// Tile M(n)=128 x N(c)=64, BK=32. 256 thr / 8 warps (4 M x 2 N).
// Grid (157, SPLIT2). Double-buffered cp.async; dn exact from raw H.
// ---------------------------------------------------------------------------
__global__ __launch_bounds__(256) void k_node_p(const float* __restrict__ H) {
    extern __shared__ float sm[];
    float* As = sm;                   // [2][128*36]
    float* Bs = sm + 2 * 4608;        // [2][32*72]
    __shared__ float sred[256];

    const int tid  = threadIdx.x;
    const int lane = tid & 31, w = tid >> 5;
    const int g = lane >> 2, q = lane & 3;
    const int wm = w & 3, wn = w >> 2;
    const int n0 = blockIdx.x * 128;
    const int sp = blockIdx.y;
    const int kbeg = sp * CHUNK2;
    const int kend = (kbeg + CHUNK2 < NE) ? (kbeg + CHUNK2) : NE;

    const int  arow   = tid >> 1;                 // 0..127
    const bool row_ok = (n0 + arow) < NN;
    const long aoff   = (long)(n0 + arow) * NE;
    const int  akb    = (tid & 1) * 16;
    const int  brow   = tid >> 3;                 // 0..31
    const int  bc0    = (tid & 7) * 4;

    float acc[2][4][4];
#pragma unroll
    for (int s2 = 0; s2 < 2; s2++)
#pragma unroll
        for (int nt = 0; nt < 4; nt++)
#pragma unroll
            for (int r = 0; r < 4; r++) acc[s2][nt][r] = 0.f;
    float dn_acc = 0.f;

    auto load = [&](int buf, int k0) {
#pragma unroll
        for (int j = 0; j < 4; j++) {
            int kf = akb + 4 * j;
            cpa16(As + buf * 4608 + arow * 36 + kf, H + aoff + k0 + kf,
                  row_ok && (k0 + kf + 4 <= NE));
        }
        int e = k0 + brow;
        bool eok = e < NE;
#pragma unroll
        for (int j = 0; j < 2; j++) {
            int cf = bc0 + 32 * j;
            cpa16(Bs + buf * 2304 + brow * 72 + cf, g_ef + e * OC + cf, eok);
        }
    };

    load(0, kbeg);
    cpa_commit();
    int buf = 0;
    for (int k0 = kbeg; k0 < kend; k0 += 32) {
        bool hn = (k0 + 32) < kend;
        if (hn) { load(buf ^ 1, k0 + 32); cpa_commit(); cpa_wait<1>(); }
        else    { cpa_wait<0>(); }
        __syncthreads();
        const float* as = As + buf * 4608;
        const float* bs = Bs + buf * 2304;
        {   // exact fp32 row-sum partial from raw H (zero-fills add 0)
            int r = tid >> 1, h = (tid & 1) * 16;
#pragma unroll
            for (int k = 0; k < 16; k++) dn_acc += as[r * 36 + h + k];
        }
#pragma unroll
        for (int ks = 0; ks < 32; ks += 8) {
            unsigned a[2][4];
#pragma unroll
            for (int s2 = 0; s2 < 2; s2++) {
                int m = wm * 32 + s2 * 16;
                a[s2][0] = tf32u(as[(m + g) * 36 + ks + q]);
                a[s2][1] = tf32u(as[(m + g + 8) * 36 + ks + q]);
                a[s2][2] = tf32u(as[(m + g) * 36 + ks + q + 4]);
                a[s2][3] = tf32u(as[(m + g + 8) * 36 + ks + q + 4]);
            }
#pragma unroll
            for (int nt = 0; nt < 4; nt++) {
                unsigned b0 = tf32u(bs[(ks + q) * 72 + wn * 32 + nt * 8 + g]);
                unsigned b1 = tf32u(bs[(ks + q + 4) * 72 + wn * 32 + nt * 8 + g]);
                mma8(acc[0][nt], a[0][0], a[0][1], a[0][2], a[0][3], b0, b1);
                mma8(acc[1][nt], a[1][0], a[1][1], a[1][2], a[1][3], b0, b1);
            }
        }
        __syncthreads();
        buf ^= 1;
    }

    sred[tid] = dn_acc;
    __syncthreads();
    if (tid < 128) {
        int n = n0 + tid;
        if (n < NN) g_dn_part[sp * NN + n] = sred[2 * tid] + sred[2 * tid + 1];
    }

    float* op = g_out_part + sp * NN * OC;
#pragma unroll
    for (int s2 = 0; s2 < 2; s2++) {
        int nA = n0 + wm * 32 + s2 * 16 + g;
        int nB = nA + 8;
#pragma unroll
        for (int nt = 0; nt < 4; nt++) {
            int c = wn * 32 + nt * 8 + 2 * q;
            if (nA < NN)
                *(float2*)&op[nA * OC + c] = make_float2(acc[s2][nt][0], acc[s2][nt][1]);
            if (nB < NN)
                *(float2*)&op[nB * OC + c] = make_float2(acc[s2][nt][2], acc[s2][nt][3]);
        }
    }
}

// Finalize pass 2: out = (sum_s part) / (sum_s dn_part)
__global__ __launch_bounds__(256) void k_fin2(float* __restrict__ out) {
    int idx = blockIdx.x * 256 + threadIdx.x;   // n*64 + c, exact cover
    int n = idx >> 6;
    float s = 0.f, d = 0.f;
#pragma unroll
    for (int sp = 0; sp < SPLIT2; sp++) {
        s += g_out_part[sp * NN * OC + idx];
        d += g_dn_part[sp * NN + n];
    }
    out[idx] = s / d;
}

// ---------------------------------------------------------------------------
extern "C" void kernel_launch(void* const* d_in, const int* in_sizes, int n_in,
                              void* d_out, int out_size) {
    const float* x     = (const float*)d_in[0];   // [20000, 128]
    const float* H     = (const float*)d_in[1];   // [20000, 10000]
    const float* theta = (const float*)d_in[2];   // [128, 64]
    float* out         = (float*)d_out;           // [20000, 64]

    cudaFuncSetAttribute(k_edge_p, cudaFuncAttributeMaxDynamicSharedMemorySize, 71680);
    cudaFuncSetAttribute(k_node_p, cudaFuncAttributeMaxDynamicSharedMemorySize, 55296);

    k_xw<<<NN / 32, 128>>>(x, theta);
    k_edge_p<<<dim3(79, SPLIT1), 256, 71680>>>(H);
    k_fin1<<<(NE * OC) / 256, 256>>>();
    k_node_p<<<dim3(157, SPLIT2), 256, 55296>>>(H);
    k_fin2<<<(NN * OC) / 256, 256>>>(out);
    (void)in_sizes; (void)n_in; (void)out_size;
}

// round 11
// speedup vs baseline: 1.0536x; 1.0536x over previous
#include <cuda_runtime.h>
#include <cstdint>

#define NN 20000
#define NE 10000
#define IC 128
#define OC 64
#define SPLIT1 8
#define SPLIT2 4
#define CHUNK1 2528   // 79 k-tiles of 32 (last split: 72 tiles)
#define CHUNK2 2528

// Scratch (device globals — no allocation in kernel_launch).
__device__ float g_xwT_hi[OC * NN];          // tf32(xw)^T        [64][20000]
__device__ float g_xwT_lo[OC * NN];          // tf32(xw-hi)^T     [64][20000]
__device__ float g_ef[NE * OC];              // tf32 edge features [E][64]
__device__ float g_ef_part[SPLIT1 * NE * OC];
__device__ float g_de_part[SPLIT1 * NE];
__device__ float g_out_part[SPLIT2 * NN * OC];
__device__ float g_dn_part[SPLIT2 * NN];

// ---------------------------------------------------------------------------
// helpers
// ---------------------------------------------------------------------------
__device__ __forceinline__ float to_tf32(float x) {
    unsigned u;
    asm("cvt.rna.tf32.f32 %0, %1;" : "=r"(u) : "f"(x));
    return __uint_as_float(u);
}
__device__ __forceinline__ unsigned tf32u(float x) {
    unsigned u;
    asm("cvt.rna.tf32.f32 %0, %1;" : "=r"(u) : "f"(x));
    return u;
}
// mma.m16n8k8 tf32: A row-major [16,8], B col-major [8,8], C fp32 [16,8]
__device__ __forceinline__ void mma8(float* c, unsigned a0, unsigned a1,
                                     unsigned a2, unsigned a3,
                                     unsigned b0, unsigned b1) {
    asm volatile(
        "mma.sync.aligned.m16n8k8.row.col.f32.tf32.tf32.f32 "
        "{%0,%1,%2,%3}, {%4,%5,%6,%7}, {%8,%9}, {%0,%1,%2,%3};\n"
        : "+f"(c[0]), "+f"(c[1]), "+f"(c[2]), "+f"(c[3])
        : "r"(a0), "r"(a1), "r"(a2), "r"(a3), "r"(b0), "r"(b1));
}
__device__ __forceinline__ void cpa16(float* dst, const float* src, bool pred) {
    unsigned sdst = (unsigned)__cvta_generic_to_shared(dst);
    int sz = pred ? 16 : 0;   // src-size 0 => 16B zero-fill
    asm volatile("cp.async.cg.shared.global [%0], [%1], 16, %2;\n"
                 :: "r"(sdst), "l"(src), "r"(sz));
}
__device__ __forceinline__ void cpa_commit() {
    asm volatile("cp.async.commit_group;\n");
}
template <int N>
__device__ __forceinline__ void cpa_wait() {
    asm volatile("cp.async.wait_group %0;\n" :: "n"(N));
}
__device__ __forceinline__ void sts128(float* dst, unsigned x, unsigned y,
                                       unsigned z, unsigned w) {
    unsigned s = (unsigned)__cvta_generic_to_shared(dst);
    asm volatile("st.shared.v4.b32 [%0], {%1,%2,%3,%4};"
                 :: "r"(s), "r"(x), "r"(y), "r"(z), "r"(w) : "memory");
}

// ---------------------------------------------------------------------------
// Kernel 1: xw = x @ theta, stored TRANSPOSED as tf32 hi/lo pairs.
// ---------------------------------------------------------------------------
__global__ __launch_bounds__(128) void k_xw(const float* __restrict__ x,
                                            const float* __restrict__ theta) {
    __shared__ float a_s[32][33];
    __shared__ float b_s[32][64];
    const int tid = threadIdx.x, rg = tid >> 3, cg = tid & 7;
    const int n0 = blockIdx.x * 32;
    float acc[2][8];
#pragma unroll
    for (int i = 0; i < 2; i++)
#pragma unroll
        for (int j = 0; j < 8; j++) acc[i][j] = 0.f;
    for (int k0 = 0; k0 < IC; k0 += 32) {
#pragma unroll
        for (int t = 0; t < 8; t++) {
            int idx = tid + t * 128, i = idx >> 5, j = idx & 31;
            a_s[j][i] = x[(n0 + i) * IC + k0 + j];
        }
#pragma unroll
        for (int t = 0; t < 4; t++) {
            int idx4 = tid + t * 128, r = idx4 >> 4, c4 = idx4 & 15;
            ((float4*)b_s[r])[c4] = ((const float4*)(theta + (k0 + r) * OC))[c4];
        }
        __syncthreads();
#pragma unroll
        for (int k = 0; k < 32; k++) {
            float a0 = a_s[k][rg * 2], a1 = a_s[k][rg * 2 + 1];
            float4 b0 = *(float4*)&b_s[k][cg * 8], b1 = *(float4*)&b_s[k][cg * 8 + 4];
            float bb[8] = {b0.x, b0.y, b0.z, b0.w, b1.x, b1.y, b1.z, b1.w};
#pragma unroll
            for (int j = 0; j < 8; j++) { acc[0][j] += a0 * bb[j]; acc[1][j] += a1 * bb[j]; }
        }
        __syncthreads();
    }
#pragma unroll
    for (int i = 0; i < 2; i++) {
        int n = n0 + rg * 2 + i;
#pragma unroll
        for (int j = 0; j < 8; j++) {
            int c = cg * 8 + j;
            float v = acc[i][j], hi = to_tf32(v), lo = to_tf32(v - hi);
            g_xwT_hi[c * NN + n] = hi;
            g_xwT_lo[c * NN + n] = lo;
        }
    }
}

// ---------------------------------------------------------------------------
// Pass 1 (partial): ef^T[c][e] += sum_{n in chunk} xwT[c][n] * H[n][e]
// Tile M(c)=64 x N(e)=128, BK=32. 256 thr / 8 warps (4 M x 2 N).
// A (xwT hi/lo) pre-rounded via cp.async. B (H) LDG->cvt->STS; de from LDG regs.
// Software-pipelined: LDG/cp.async for tile k+1 issued before mma on tile k.
// ---------------------------------------------------------------------------
__global__ __launch_bounds__(256) void k_edge_p(const float* __restrict__ H) {
    extern __shared__ float sm[];
    float* Ah = sm;                   // [2][64*36]
    float* Al = sm + 2 * 2304;        // [2][64*36]
    float* Bs = sm + 4 * 2304;        // [2][32*136]
    __shared__ float sred[256];

    const int tid  = threadIdx.x;
    const int lane = tid & 31, w = tid >> 5;
    const int g = lane >> 2, q = lane & 3;
    const int wm = w & 3, wn = w >> 2;
    const int e0 = blockIdx.x * 128;
    const int sp = blockIdx.y;
    const int kbeg = sp * CHUNK1;
    const int kend = (kbeg + CHUNK1 < NN) ? (kbeg + CHUNK1) : NN;
    const int nk = (kend - kbeg) >> 5;   // chunk sizes are 32-divisible

    const int arow = tid >> 3;        // 0..31 (+32)
    const int ak4  = (tid & 7) * 4;
    const int brow = tid >> 3;        // H row within k-tile
    const int bc0  = (tid & 7) * 4;   // e-column base

    float acc[8][4];
#pragma unroll
    for (int nt = 0; nt < 8; nt++)
#pragma unroll
        for (int r = 0; r < 4; r++) acc[nt][r] = 0.f;
    float dep[16];
#pragma unroll
    for (int i = 0; i < 16; i++) dep[i] = 0.f;
    float4 hreg[4];

    auto cpaA = [&](int buf, int k0) {
#pragma unroll
        for (int i = 0; i < 2; i++) {
            int r = arow + 32 * i;
            long go = (long)r * NN + k0 + ak4;
            cpa16(Ah + buf * 2304 + r * 36 + ak4, g_xwT_hi + go, true);
            cpa16(Al + buf * 2304 + r * 36 + ak4, g_xwT_lo + go, true);
        }
    };
    auto ldgB = [&](int k0) {
        long ho = (long)(k0 + brow) * NE;
#pragma unroll
        for (int j = 0; j < 4; j++) {
            int e = e0 + bc0 + 32 * j;
            hreg[j] = (e < NE) ? *(const float4*)(H + ho + e)
                               : make_float4(0.f, 0.f, 0.f, 0.f);
        }
    };
    auto stsB = [&](int buf) {
#pragma unroll
        for (int j = 0; j < 4; j++) {
            dep[4 * j + 0] += hreg[j].x;
            dep[4 * j + 1] += hreg[j].y;
            dep[4 * j + 2] += hreg[j].z;
            dep[4 * j + 3] += hreg[j].w;
            sts128(Bs + buf * 4352 + brow * 136 + bc0 + 32 * j,
                   tf32u(hreg[j].x), tf32u(hreg[j].y),
                   tf32u(hreg[j].z), tf32u(hreg[j].w));
        }
    };
    auto compute = [&](int buf) {
        const float* ah = Ah + buf * 2304;
        const float* al = Al + buf * 2304;
        const float* bs = Bs + buf * 4352;
#pragma unroll
        for (int ks = 0; ks < 32; ks += 8) {
            const int ar = wm * 16;
            unsigned h0 = __float_as_uint(ah[(ar + g) * 36 + ks + q]);
            unsigned h1 = __float_as_uint(ah[(ar + g + 8) * 36 + ks + q]);
            unsigned h2 = __float_as_uint(ah[(ar + g) * 36 + ks + q + 4]);
            unsigned h3 = __float_as_uint(ah[(ar + g + 8) * 36 + ks + q + 4]);
            unsigned l0 = __float_as_uint(al[(ar + g) * 36 + ks + q]);
            unsigned l1 = __float_as_uint(al[(ar + g + 8) * 36 + ks + q]);
            unsigned l2 = __float_as_uint(al[(ar + g) * 36 + ks + q + 4]);
            unsigned l3 = __float_as_uint(al[(ar + g + 8) * 36 + ks + q + 4]);
#pragma unroll
            for (int nt = 0; nt < 8; nt++) {
                unsigned b0 = __float_as_uint(bs[(ks + q) * 136 + wn * 64 + nt * 8 + g]);
                unsigned b1 = __float_as_uint(bs[(ks + q + 4) * 136 + wn * 64 + nt * 8 + g]);
                mma8(acc[nt], h0, h1, h2, h3, b0, b1);
                mma8(acc[nt], l0, l1, l2, l3, b0, b1);
            }
        }
    };

    // prolog: fill buffer 0
    ldgB(kbeg);
    cpaA(0, kbeg); cpa_commit();
    stsB(0);
    cpa_wait<0>(); __syncthreads();

    for (int it = 0; it < nk; it++) {
        const int buf = it & 1, nxt = buf ^ 1;
        const bool more = (it + 1 < nk);
        if (more) {
            int k1 = kbeg + (it + 1) * 32;
            ldgB(k1);                       // long-latency, overlaps mma below
            cpaA(nxt, k1); cpa_commit();
        }
        compute(buf);
        if (more) {
            stsB(nxt);
            cpa_wait<0>(); __syncthreads();
        }
    }
    __syncthreads();   // everyone done with Bs before reuse as staging

    // de reduction: stage per-thread partials into (dead) Bs, then col-reduce.
    {
        float* stg = Bs;   // 256*16 floats = 16 KB, fits in Bs region
#pragma unroll
        for (int i = 0; i < 16; i++) stg[tid * 16 + i] = dep[i];
        __syncthreads();
        if (tid < 128) {
            int col = tid;                       // e0 + col
            int s = (col & 31) >> 2;
            int jc = ((col >> 5) << 2) + (col & 3);
            float v = 0.f;
#pragma unroll
            for (int r = 0; r < 32; r++) v += stg[(s + 8 * r) * 16 + jc];
            int e = e0 + col;
            if (e < NE) g_de_part[sp * NE + e] = v;
        }
    }

    float* op = g_ef_part + sp * NE * OC;
    const int c0 = wm * 16 + g;
#pragma unroll
    for (int nt = 0; nt < 8; nt++) {
        int eA = e0 + wn * 64 + nt * 8 + 2 * q;
        int eB = eA + 1;
        if (eA < NE) { op[eA * OC + c0] = acc[nt][0]; op[eA * OC + c0 + 8] = acc[nt][2]; }
        if (eB < NE) { op[eB * OC + c0] = acc[nt][1]; op[eB * OC + c0 + 8] = acc[nt][3]; }
    }
    (void)sred;
}

// Finalize pass 1: ef = tf32((sum_s part) / (sum_s de_part))  [tf32 so pass 2
// fragment loads need no cvt]
__global__ __launch_bounds__(256) void k_fin1() {
    int idx = blockIdx.x * 256 + threadIdx.x;   // e*64 + c, exact cover
    int e = idx >> 6;
    float s = 0.f, d = 0.f;
#pragma unroll
    for (int sp = 0; sp < SPLIT1; sp++) {
        s += g_ef_part[sp * NE * OC + idx];
        d += g_de_part[sp * NE + e];
    }
    g_ef[idx] = to_tf32(s / d);
}

// ---------------------------------------------------------------------------
// Pass 2 (partial): out[n][c] += sum_{e in chunk} H[n][e] * ef[e][c]
// Tile M(n)=128 x N(c)=64, BK=32. 256 thr / 8 warps (4 M x 2 N).
// A (H) LDG->cvt->STS with dn from LDG regs; B (g_ef, pre-rounded) cp.async.
// Software-pipelined like pass 1.
// ---------------------------------------------------------------------------
__global__ __launch_bounds__(256) void k_node_p(const float* __restrict__ H) {
    extern __shared__ float sm[];
    float* As = sm;                   // [2][128*36]
    float* Bs = sm + 2 * 4608;        // [2][32*72]
    __shared__ float sred[256];

    const int tid  = threadIdx.x;
    const int lane = tid & 31, w = tid >> 5;
    const int g = lane >> 2, q = lane & 3;
    const int wm = w & 3, wn = w >> 2;
    const int n0 = blockIdx.x * 128;
    const int sp = blockIdx.y;
    const int kbeg = sp * CHUNK2;
    const int kend = (kbeg + CHUNK2 < NE) ? (kbeg + CHUNK2) : NE;
    const int nk = (kend - kbeg + 31) >> 5;   // last split has a partial tile

    const int  arow   = tid >> 1;                 // 0..127
    const bool row_ok = (n0 + arow) < NN;
    const long aoff   = (long)(n0 + arow) * NE;
    const int  akb    = (tid & 1) * 16;
    const int  brow   = tid >> 3;                 // 0..31
    const int  bc0    = (tid & 7) * 4;

    float acc[2][4][4];
#pragma unroll
    for (int s2 = 0; s2 < 2; s2++)
#pragma unroll
        for (int nt = 0; nt < 4; nt++)
#pragma unroll
            for (int r = 0; r < 4; r++) acc[s2][nt][r] = 0.f;
    float dn_acc = 0.f;
    float4 areg[4];

    auto ldgA = [&](int k0) {
#pragma unroll
        for (int j = 0; j < 4; j++) {
            int kf = akb + 4 * j;
            areg[j] = (row_ok && (k0 + kf + 4 <= NE))
                          ? *(const float4*)(H + aoff + k0 + kf)
                          : make_float4(0.f, 0.f, 0.f, 0.f);
        }
    };
    auto stsA = [&](int buf) {
#pragma unroll
        for (int j = 0; j < 4; j++) {
            dn_acc += (areg[j].x + areg[j].y) + (areg[j].z + areg[j].w);
            sts128(As + buf * 4608 + arow * 36 + akb + 4 * j,
                   tf32u(areg[j].x), tf32u(areg[j].y),
                   tf32u(areg[j].z), tf32u(areg[j].w));
        }
    };
    auto cpaB = [&](int buf, int k0) {
        int e = k0 + brow;
        bool eok = e < NE;
#pragma unroll
        for (int j = 0; j < 2; j++) {
            int cf = bc0 + 32 * j;
            cpa16(Bs + buf * 2304 + brow * 72 + cf, g_ef + e * OC + cf, eok);
        }
    };
    auto compute = [&](int buf) {
        const float* as = As + buf * 4608;
        const float* bs = Bs + buf * 2304;
#pragma unroll
        for (int ks = 0; ks < 32; ks += 8) {
            unsigned a[2][4];
#pragma unroll
            for (int s2 = 0; s2 < 2; s2++) {
                int m = wm * 32 + s2 * 16;
                a[s2][0] = __float_as_uint(as[(m + g) * 36 + ks + q]);
                a[s2][1] = __float_as_uint(as[(m + g + 8) * 36 + ks + q]);
                a[s2][2] = __float_as_uint(as[(m + g) * 36 + ks + q + 4]);
                a[s2][3] = __float_as_uint(as[(m + g + 8) * 36 + ks + q + 4]);
            }
#pragma unroll
            for (int nt = 0; nt < 4; nt++) {
                unsigned b0 = __float_as_uint(bs[(ks + q) * 72 + wn * 32 + nt * 8 + g]);
                unsigned b1 = __float_as_uint(bs[(ks + q + 4) * 72 + wn * 32 + nt * 8 + g]);
                mma8(acc[0][nt], a[0][0], a[0][1], a[0][2], a[0][3], b0, b1);
                mma8(acc[1][nt], a[1][0], a[1][1], a[1][2], a[1][3], b0, b1);
            }
        }
    };

    // prolog
    ldgA(kbeg);
    cpaB(0, kbeg); cpa_commit();
    stsA(0);
    cpa_wait<0>(); __syncthreads();

    for (int it = 0; it < nk; it++) {
        const int buf = it & 1, nxt = buf ^ 1;
        const bool more = (it + 1 < nk);
        if (more) {
            int k1 = kbeg + (it + 1) * 32;
            ldgA(k1);
            cpaB(nxt, k1); cpa_commit();
        }
        compute(buf);
        if (more) {
            stsA(nxt);
            cpa_wait<0>(); __syncthreads();
        }
    }

    sred[tid] = dn_acc;
    __syncthreads();
    if (tid < 128) {
        int n = n0 + tid;
        if (n < NN) g_dn_part[sp * NN + n] = sred[2 * tid] + sred[2 * tid + 1];
    }

    float* op = g_out_part + sp * NN * OC;
#pragma unroll
    for (int s2 = 0; s2 < 2; s2++) {
        int nA = n0 + wm * 32 + s2 * 16 + g;
        int nB = nA + 8;
#pragma unroll
        for (int nt = 0; nt < 4; nt++) {
            int c = wn * 32 + nt * 8 + 2 * q;
            if (nA < NN)
                *(float2*)&op[nA * OC + c] = make_float2(acc[s2][nt][0], acc[s2][nt][1]);
            if (nB < NN)
                *(float2*)&op[nB * OC + c] = make_float2(acc[s2][nt][2], acc[s2][nt][3]);
        }
    }
}

// Finalize pass 2: out = (sum_s part) / (sum_s dn_part)
__global__ __launch_bounds__(256) void k_fin2(float* __restrict__ out) {
    int idx = blockIdx.x * 256 + threadIdx.x;   // n*64 + c, exact cover
    int n = idx >> 6;
    float s = 0.f, d = 0.f;
#pragma unroll
    for (int sp = 0; sp < SPLIT2; sp++) {
        s += g_out_part[sp * NN * OC + idx];
        d += g_dn_part[sp * NN + n];
    }
    out[idx] = s / d;
}

// ---------------------------------------------------------------------------
extern "C" void kernel_launch(void* const* d_in, const int* in_sizes, int n_in,
                              void* d_out, int out_size) {
    const float* x     = (const float*)d_in[0];   // [20000, 128]
    const float* H     = (const float*)d_in[1];   // [20000, 10000]
    const float* theta = (const float*)d_in[2];   // [128, 64]
    float* out         = (float*)d_out;           // [20000, 64]

    cudaFuncSetAttribute(k_edge_p, cudaFuncAttributeMaxDynamicSharedMemorySize, 71680);
    cudaFuncSetAttribute(k_node_p, cudaFuncAttributeMaxDynamicSharedMemorySize, 55296);

    k_xw<<<NN / 32, 128>>>(x, theta);
    k_edge_p<<<dim3(79, SPLIT1), 256, 71680>>>(H);
    k_fin1<<<(NE * OC) / 256, 256>>>();
    k_node_p<<<dim3(157, SPLIT2), 256, 55296>>>(H);
    k_fin2<<<(NN * OC) / 256, 256>>>(out);
    (void)in_sizes; (void)n_in; (void)out_size;
}

// round 12
// speedup vs baseline: 1.2537x; 1.1899x over previous
#include <cuda_runtime.h>
#include <cuda_fp16.h>
#include <cstdint>

#define NN 20000
#define NE 10000
#define IC 128
#define OC 64
#define SPLIT1 8
#define SPLIT2 4
#define CHUNK1 2528    // pass1 n-chunk (79 tiles; last split 72)
#define CHUNK2 2528    // pass2 e-chunk
#define NEP1 10048     // 157*64 pass1 padded e stride
#define NEP2 10016     // 313*32 pass2 padded e stride (fp16 row stride)
#define ASTR 40        // A smem stride (halves)
#define BSTR1 38       // pass1 B smem stride (halves)

// Scratch (device globals — no allocation in kernel_launch).
__device__ __half g_xwT[128 * NN];          // rows 0-63: hi(xw)^T, 64-127: lo
__device__ __half g_efT[OC * NEP2];         // fp16 edge features [c][e], e>=NE zero
__device__ float  g_p1[SPLIT1 * 128 * NEP1];
__device__ float  g_de_part[SPLIT1 * NE];
__device__ float  g_out_part[SPLIT2 * NN * OC];
__device__ float  g_dn_part[SPLIT2 * NN];

// ---------------- helpers ----------------
__device__ __forceinline__ unsigned h2u(float lo, float hi) {
    __half2 h = __floats2half2_rn(lo, hi);
    return *(unsigned*)&h;
}
__device__ __forceinline__ void mma16(float* c, unsigned a0, unsigned a1,
                                      unsigned a2, unsigned a3,
                                      unsigned b0, unsigned b1) {
    asm volatile(
        "mma.sync.aligned.m16n8k16.row.col.f32.f16.f16.f32 "
        "{%0,%1,%2,%3}, {%4,%5,%6,%7}, {%8,%9}, {%0,%1,%2,%3};\n"
        : "+f"(c[0]), "+f"(c[1]), "+f"(c[2]), "+f"(c[3])
        : "r"(a0), "r"(a1), "r"(a2), "r"(a3), "r"(b0), "r"(b1));
}
__device__ __forceinline__ void cpa16(void* dst, const void* src, bool pred) {
    unsigned sdst = (unsigned)__cvta_generic_to_shared(dst);
    int sz = pred ? 16 : 0;
    asm volatile("cp.async.cg.shared.global [%0], [%1], 16, %2;\n"
                 :: "r"(sdst), "l"(src), "r"(sz));
}
__device__ __forceinline__ void cpa_commit() { asm volatile("cp.async.commit_group;\n"); }
template <int N> __device__ __forceinline__ void cpa_wait() {
    asm volatile("cp.async.wait_group %0;\n" :: "n"(N));
}
__device__ __forceinline__ void sts16(__half* dst, __half v) {
    unsigned s = (unsigned)__cvta_generic_to_shared(dst);
    asm volatile("st.shared.u16 [%0], %1;" :: "r"(s), "h"(__half_as_ushort(v)) : "memory");
}
__device__ __forceinline__ void sts128(__half* dst, unsigned x, unsigned y,
                                       unsigned z, unsigned w) {
    unsigned s = (unsigned)__cvta_generic_to_shared(dst);
    asm volatile("st.shared.v4.b32 [%0], {%1,%2,%3,%4};"
                 :: "r"(s), "r"(x), "r"(y), "r"(z), "r"(w) : "memory");
}
__device__ __forceinline__ unsigned ldsu(const __half* p) {
    return *(const unsigned*)p;
}

// ---------------------------------------------------------------------------
// Kernel 1: xw = x @ theta (fp32), stored transposed as fp16 hi/lo rows.
// ---------------------------------------------------------------------------
__global__ __launch_bounds__(128) void k_xw(const float* __restrict__ x,
                                            const float* __restrict__ theta) {
    __shared__ float a_s[32][33];
    __shared__ float b_s[32][64];
    const int tid = threadIdx.x, rg = tid >> 3, cg = tid & 7;
    const int n0 = blockIdx.x * 32;
    float acc[2][8];
#pragma unroll
    for (int i = 0; i < 2; i++)
#pragma unroll
        for (int j = 0; j < 8; j++) acc[i][j] = 0.f;
    for (int k0 = 0; k0 < IC; k0 += 32) {
#pragma unroll
        for (int t = 0; t < 8; t++) {
            int idx = tid + t * 128, i = idx >> 5, j = idx & 31;
            a_s[j][i] = x[(n0 + i) * IC + k0 + j];
        }
#pragma unroll
        for (int t = 0; t < 4; t++) {
            int idx4 = tid + t * 128, r = idx4 >> 4, c4 = idx4 & 15;
            ((float4*)b_s[r])[c4] = ((const float4*)(theta + (k0 + r) * OC))[c4];
        }
        __syncthreads();
#pragma unroll
        for (int k = 0; k < 32; k++) {
            float a0 = a_s[k][rg * 2], a1 = a_s[k][rg * 2 + 1];
            float4 b0 = *(float4*)&b_s[k][cg * 8], b1 = *(float4*)&b_s[k][cg * 8 + 4];
            float bb[8] = {b0.x, b0.y, b0.z, b0.w, b1.x, b1.y, b1.z, b1.w};
#pragma unroll
            for (int j = 0; j < 8; j++) { acc[0][j] += a0 * bb[j]; acc[1][j] += a1 * bb[j]; }
        }
        __syncthreads();
    }
#pragma unroll
    for (int i = 0; i < 2; i++) {
        int n = n0 + rg * 2 + i;
#pragma unroll
        for (int j = 0; j < 8; j++) {
            int c = cg * 8 + j;
            float v = acc[i][j];
            __half hi = __float2half_rn(v);
            __half lo = __float2half_rn(v - __half2float(hi));
            g_xwT[c * NN + n] = hi;
            g_xwT[(c + 64) * NN + n] = lo;
        }
    }
}

// ---------------------------------------------------------------------------
// Pass 1: P[r][e] = sum_{n in chunk} xwT_stack[r][n] * H[n][e]
//   A[128r][32n] fp16 via cp.async (pre-rounded); B[64e][32n] fp16 = H^T via
//   LDG + cvt + b16 scatter STS. de exact fp32 from LDG regs.
// Tile M=128 x N=64 x BK=32. 256 thr / 8 warps (4M x 2N). Grid (157, SPLIT1).
// ---------------------------------------------------------------------------
__global__ __launch_bounds__(256) void k_edge_h(const float* __restrict__ H) {
    extern __shared__ char smc[];
    __half* Ah = (__half*)smc;                       // [2][128*ASTR]
    __half* Bs = (__half*)(smc + 2 * 128 * ASTR * 2);// [2][64*BSTR1]
    float*  stg = (float*)Bs;                        // reuse after mainloop

    const int tid = threadIdx.x;
    const int lane = tid & 31, w = tid >> 5;
    const int g = lane >> 2, q = lane & 3;
    const int wm = w & 3, wn = w >> 2;
    const int e0 = blockIdx.x * 64;
    const int sp = blockIdx.y;
    const int kbeg = sp * CHUNK1;
    const int kend = (kbeg + CHUNK1 < NN) ? (kbeg + CHUNK1) : NN;
    const int nk = (kend - kbeg) >> 5;

    // A cp.async mapping: 512 granules, 2/thread
    const int ar = tid >> 1;              // row 0..127
    const int ag = (tid & 1) * 2;         // granule pair base (x8 halves)
    // B loader mapping: 16 e-blocks x 16 n
    const int t15 = tid & 15;             // e-block
    const int npart = tid >> 4;           // n 0..15 (+16)
    const int e4 = t15 * 4;
    const bool eok = (e0 + e4) < NE;      // NE % 4 == 0 -> whole float4 in/out

    float acc[2][4][4];
#pragma unroll
    for (int s2 = 0; s2 < 2; s2++)
#pragma unroll
        for (int nt = 0; nt < 4; nt++)
#pragma unroll
            for (int r = 0; r < 4; r++) acc[s2][nt][r] = 0.f;
    float dep[4] = {0.f, 0.f, 0.f, 0.f};
    float4 h0v, h1v;

    auto cpaA = [&](int buf, int k0) {
        __half* base = Ah + buf * 128 * ASTR + ar * ASTR;
        const __half* src = g_xwT + (long)ar * NN + k0;
#pragma unroll
        for (int j = 0; j < 2; j++)
            cpa16(base + (ag + j) * 8, src + (ag + j) * 8, true);
    };
    auto ldgB = [&](int k0) {
        h0v = eok ? *(const float4*)(H + (long)(k0 + npart) * NE + e0 + e4)
                  : make_float4(0.f, 0.f, 0.f, 0.f);
        h1v = eok ? *(const float4*)(H + (long)(k0 + npart + 16) * NE + e0 + e4)
                  : make_float4(0.f, 0.f, 0.f, 0.f);
    };
    auto stsB = [&](int buf) {
        __half* base = Bs + buf * 64 * BSTR1;
        float a0[4] = {h0v.x, h0v.y, h0v.z, h0v.w};
        float a1[4] = {h1v.x, h1v.y, h1v.z, h1v.w};
#pragma unroll
        for (int c = 0; c < 4; c++) {
            dep[c] += a0[c] + a1[c];
            sts16(base + (e4 + c) * BSTR1 + npart, __float2half_rn(a0[c]));
            sts16(base + (e4 + c) * BSTR1 + npart + 16, __float2half_rn(a1[c]));
        }
    };
    auto compute = [&](int buf) {
        const __half* ah = Ah + buf * 128 * ASTR;
        const __half* bs = Bs + buf * 64 * BSTR1;
#pragma unroll
        for (int ks = 0; ks < 2; ks++) {
            unsigned a[2][4];
#pragma unroll
            for (int s2 = 0; s2 < 2; s2++) {
                int m = wm * 32 + s2 * 16;
                const __half* p0 = ah + (m + g) * ASTR + ks * 16 + 2 * q;
                const __half* p1 = ah + (m + g + 8) * ASTR + ks * 16 + 2 * q;
                a[s2][0] = ldsu(p0);
                a[s2][1] = ldsu(p1);
                a[s2][2] = ldsu(p0 + 8);
                a[s2][3] = ldsu(p1 + 8);
            }
#pragma unroll
            for (int nt = 0; nt < 4; nt++) {
                const __half* pb = bs + (wn * 32 + nt * 8 + g) * BSTR1 + ks * 16 + 2 * q;
                unsigned b0 = ldsu(pb), b1 = ldsu(pb + 8);
                mma16(acc[0][nt], a[0][0], a[0][1], a[0][2], a[0][3], b0, b1);
                mma16(acc[1][nt], a[1][0], a[1][1], a[1][2], a[1][3], b0, b1);
            }
        }
    };

    // prolog
    ldgB(kbeg);
    cpaA(0, kbeg); cpa_commit();
    stsB(0);
    cpa_wait<0>(); __syncthreads();

    for (int it = 0; it < nk; it++) {
        const int buf = it & 1, nxt = buf ^ 1;
        const bool more = (it + 1 < nk);
        if (more) {
            int k1 = kbeg + (it + 1) * 32;
            ldgB(k1);
            cpaA(nxt, k1); cpa_commit();
        }
        compute(buf);
        if (more) {
            stsB(nxt);
            cpa_wait<0>(); __syncthreads();
        }
    }
    __syncthreads();

    // de reduction via staging (Bs is dead)
#pragma unroll
    for (int c = 0; c < 4; c++) stg[tid * 4 + c] = dep[c];
    __syncthreads();
    if (tid < 64) {
        float v = 0.f;
#pragma unroll
        for (int np = 0; np < 16; np++)
            v += stg[(np * 16 + (tid >> 2)) * 4 + (tid & 3)];
        int e = e0 + tid;
        if (e < NE) g_de_part[sp * NE + e] = v;
    }

    // store raw fp32 partials [sp][row r][e]
    float* op = g_p1 + (long)sp * 128 * NEP1;
#pragma unroll
    for (int s2 = 0; s2 < 2; s2++) {
        int r0 = wm * 32 + s2 * 16 + g;
#pragma unroll
        for (int nt = 0; nt < 4; nt++) {
            int e = e0 + wn * 32 + nt * 8 + 2 * q;
            *(float2*)&op[(long)r0 * NEP1 + e] = make_float2(acc[s2][nt][0], acc[s2][nt][1]);
            *(float2*)&op[(long)(r0 + 8) * NEP1 + e] = make_float2(acc[s2][nt][2], acc[s2][nt][3]);
        }
    }
}

// Finalize 1: efT[c][e] = fp16((sum_sp(hi+lo)) / sum_sp de); zero-pad e>=NE.
__global__ __launch_bounds__(256) void k_fin1() {
    int e = blockIdx.x * 256 + threadIdx.x;
    int c = blockIdx.y;
    if (e >= NEP2) return;
    if (e >= NE) { g_efT[c * NEP2 + e] = __ushort_as_half(0); return; }
    float s = 0.f, d = 0.f;
#pragma unroll
    for (int sp = 0; sp < SPLIT1; sp++) {
        s += g_p1[((long)sp * 128 + c) * NEP1 + e];
        s += g_p1[((long)sp * 128 + c + 64) * NEP1 + e];
        d += g_de_part[sp * NE + e];
    }
    g_efT[c * NEP2 + e] = __float2half_rn(s / d);
}

// ---------------------------------------------------------------------------
// Pass 2: out[n][c] += sum_{e in chunk} H[n][e] * efT[c][e]
//   A[128n][32e] fp16 = H via LDG+cvt+STS.128 (dn exact from LDG regs)
//   B[64c][32e] fp16 = g_efT via cp.async.
// Tile M=128 x N=64 x BK=32. 256 thr / 8 warps (4M x 2N). Grid (157, SPLIT2).
// ---------------------------------------------------------------------------
__global__ __launch_bounds__(256) void k_node_h(const float* __restrict__ H) {
    extern __shared__ char smc[];
    __half* As = (__half*)smc;                        // [2][128*ASTR]
    __half* Bs = (__half*)(smc + 2 * 128 * ASTR * 2); // [2][64*ASTR]
    __shared__ float sred[256];

    const int tid = threadIdx.x;
    const int lane = tid & 31, w = tid >> 5;
    const int g = lane >> 2, q = lane & 3;
    const int wm = w & 3, wn = w >> 2;
    const int n0 = blockIdx.x * 128;
    const int sp = blockIdx.y;
    const int kbeg = sp * CHUNK2;
    const int kend = (kbeg + CHUNK2 < NE) ? (kbeg + CHUNK2) : NE;
    const int nk = (kend - kbeg + 31) >> 5;

    const int  arow   = tid >> 1;
    const bool row_ok = (n0 + arow) < NN;
    const long aoff   = (long)(n0 + arow) * NE;
    const int  akb    = (tid & 1) * 16;   // k-half base (halves)
    const int  brow   = tid >> 2;         // B row (c) 0..63
    const int  bg     = tid & 3;          // granule

    float acc[2][4][4];
#pragma unroll
    for (int s2 = 0; s2 < 2; s2++)
#pragma unroll
        for (int nt = 0; nt < 4; nt++)
#pragma unroll
            for (int r = 0; r < 4; r++) acc[s2][nt][r] = 0.f;
    float dn_acc = 0.f;
    float4 areg[4];

    auto ldgA = [&](int k0) {
#pragma unroll
        for (int j = 0; j < 4; j++) {
            int kf = akb + 4 * j;
            areg[j] = (row_ok && (k0 + kf + 4 <= NE))
                          ? *(const float4*)(H + aoff + k0 + kf)
                          : make_float4(0.f, 0.f, 0.f, 0.f);
        }
    };
    auto stsA = [&](int buf) {
        __half* dst = As + buf * 128 * ASTR + arow * ASTR + akb;
        unsigned u[8];
#pragma unroll
        for (int j = 0; j < 4; j++) {
            dn_acc += (areg[j].x + areg[j].y) + (areg[j].z + areg[j].w);
            u[2 * j]     = h2u(areg[j].x, areg[j].y);
            u[2 * j + 1] = h2u(areg[j].z, areg[j].w);
        }
        sts128(dst, u[0], u[1], u[2], u[3]);
        sts128(dst + 8, u[4], u[5], u[6], u[7]);
    };
    auto cpaB = [&](int buf, int k0) {
        cpa16(Bs + buf * 64 * ASTR + brow * ASTR + bg * 8,
              g_efT + (long)brow * NEP2 + k0 + bg * 8, true);
    };
    auto compute = [&](int buf) {
        const __half* as = As + buf * 128 * ASTR;
        const __half* bs = Bs + buf * 64 * ASTR;
#pragma unroll
        for (int ks = 0; ks < 2; ks++) {
            unsigned a[2][4];
#pragma unroll
            for (int s2 = 0; s2 < 2; s2++) {
                int m = wm * 32 + s2 * 16;
                const __half* p0 = as + (m + g) * ASTR + ks * 16 + 2 * q;
                const __half* p1 = as + (m + g + 8) * ASTR + ks * 16 + 2 * q;
                a[s2][0] = ldsu(p0);
                a[s2][1] = ldsu(p1);
                a[s2][2] = ldsu(p0 + 8);
                a[s2][3] = ldsu(p1 + 8);
            }
#pragma unroll
            for (int nt = 0; nt < 4; nt++) {
                const __half* pb = bs + (wn * 32 + nt * 8 + g) * ASTR + ks * 16 + 2 * q;
                unsigned b0 = ldsu(pb), b1 = ldsu(pb + 8);
                mma16(acc[0][nt], a[0][0], a[0][1], a[0][2], a[0][3], b0, b1);
                mma16(acc[1][nt], a[1][0], a[1][1], a[1][2], a[1][3], b0, b1);
            }
        }
    };

    // prolog
    ldgA(kbeg);
    cpaB(0, kbeg); cpa_commit();
    stsA(0);
    cpa_wait<0>(); __syncthreads();

    for (int it = 0; it < nk; it++) {
        const int buf = it & 1, nxt = buf ^ 1;
        const bool more = (it + 1 < nk);
        if (more) {
            int k1 = kbeg + (it + 1) * 32;
            ldgA(k1);
            cpaB(nxt, k1); cpa_commit();
        }
        compute(buf);
        if (more) {
            stsA(nxt);
            cpa_wait<0>(); __syncthreads();
        }
    }

    sred[tid] = dn_acc;
    __syncthreads();
    if (tid < 128) {
        int n = n0 + tid;
        if (n < NN) g_dn_part[sp * NN + n] = sred[2 * tid] + sred[2 * tid + 1];
    }

    float* op = g_out_part + (long)sp * NN * OC;
#pragma unroll
    for (int s2 = 0; s2 < 2; s2++) {
        int nA = n0 + wm * 32 + s2 * 16 + g;
        int nB = nA + 8;
#pragma unroll
        for (int nt = 0; nt < 4; nt++) {
            int c = wn * 32 + nt * 8 + 2 * q;
            if (nA < NN)
                *(float2*)&op[(long)nA * OC + c] = make_float2(acc[s2][nt][0], acc[s2][nt][1]);
            if (nB < NN)
                *(float2*)&op[(long)nB * OC + c] = make_float2(acc[s2][nt][2], acc[s2][nt][3]);
        }
    }
}

// Finalize 2: out = (sum_sp part) / (sum_sp dn)
__global__ __launch_bounds__(256) void k_fin2(float* __restrict__ out) {
    int idx = blockIdx.x * 256 + threadIdx.x;
    int n = idx >> 6;
    float s = 0.f, d = 0.f;
#pragma unroll
    for (int sp = 0; sp < SPLIT2; sp++) {
        s += g_out_part[(long)sp * NN * OC + idx];
        d += g_dn_part[sp * NN + n];
    }
    out[idx] = s / d;
}

// ---------------------------------------------------------------------------
extern "C" void kernel_launch(void* const* d_in, const int* in_sizes, int n_in,
                              void* d_out, int out_size) {
    const float* x     = (const float*)d_in[0];   // [20000, 128]
    const float* H     = (const float*)d_in[1];   // [20000, 10000]
    const float* theta = (const float*)d_in[2];   // [128, 64]
    float* out         = (float*)d_out;           // [20000, 64]

    const int smem1 = 2 * 128 * ASTR * 2 + 2 * 64 * BSTR1 * 2;  // 30208 B
    const int smem2 = 2 * 128 * ASTR * 2 + 2 * 64 * ASTR * 2;   // 30720 B

    k_xw<<<NN / 32, 128>>>(x, theta);
    k_edge_h<<<dim3(157, SPLIT1), 256, smem1>>>(H);
    k_fin1<<<dim3((NEP2 + 255) / 256, OC), 256>>>();
    k_node_h<<<dim3(157, SPLIT2), 256, smem2>>>(H);
    k_fin2<<<(NN * OC) / 256, 256>>>(out);
    (void)in_sizes; (void)n_in; (void)out_size;
}

// round 16
// speedup vs baseline: 1.5038x; 1.1995x over previous
#include <cuda_runtime.h>
#include <cuda_fp16.h>
#include <cstdint>

#define NN 20000
#define NE 10000
#define IC 128
#define OC 64
#define SPLIT1 12
#define SPLIT2 8
#define CHUNK1 1696    // 53 k-tiles of 32 (last split: 42)
#define CHUNK2 1280    // 40 k-tiles (last split: 33, partial-tile padded)
#define NEP1 10048     // 157*64: pass-1 partial stride
#define NEP2 10240     // 8*1280: pass-2 padded efT stride (halves)
#define ASTR 40        // smem stride for 32-half rows (pad 8)
#define BSTR 72        // pass-1 B smem stride for 64-half rows (pad 8)

// Scratch (device globals — no allocation in kernel_launch).
__device__ __half g_xwT[128 * NN];          // rows 0-63: hi(xw)^T, 64-127: lo
__device__ __half g_efT[OC * NEP2];         // fp16 edge features [c][e], zero-padded
__device__ float  g_p1[SPLIT1 * 128 * NEP1];
__device__ float  g_de_part[SPLIT1 * NE];
__device__ float  g_out_part[SPLIT2 * NN * OC];
__device__ float  g_dn_part[SPLIT2 * NN];

// ---------------- helpers ----------------
__device__ __forceinline__ unsigned h2u(float lo, float hi) {
    __half2 h = __floats2half2_rn(lo, hi);
    return *(unsigned*)&h;
}
__device__ __forceinline__ void mma16(float* c, unsigned a0, unsigned a1,
                                      unsigned a2, unsigned a3,
                                      unsigned b0, unsigned b1) {
    asm volatile(
        "mma.sync.aligned.m16n8k16.row.col.f32.f16.f16.f32 "
        "{%0,%1,%2,%3}, {%4,%5,%6,%7}, {%8,%9}, {%0,%1,%2,%3};\n"
        : "+f"(c[0]), "+f"(c[1]), "+f"(c[2]), "+f"(c[3])
        : "r"(a0), "r"(a1), "r"(a2), "r"(a3), "r"(b0), "r"(b1));
}
__device__ __forceinline__ void ldsm4(unsigned* r, const __half* p) {
    unsigned a = (unsigned)__cvta_generic_to_shared(p);
    asm volatile("ldmatrix.sync.aligned.m8n8.x4.shared.b16 {%0,%1,%2,%3}, [%4];"
                 : "=r"(r[0]), "=r"(r[1]), "=r"(r[2]), "=r"(r[3]) : "r"(a));
}
__device__ __forceinline__ void ldsm4t(unsigned* r, const __half* p) {
    unsigned a = (unsigned)__cvta_generic_to_shared(p);
    asm volatile("ldmatrix.sync.aligned.m8n8.x4.trans.shared.b16 {%0,%1,%2,%3}, [%4];"
                 : "=r"(r[0]), "=r"(r[1]), "=r"(r[2]), "=r"(r[3]) : "r"(a));
}
__device__ __forceinline__ void cpa16(void* dst, const void* src, bool pred) {
    unsigned sdst = (unsigned)__cvta_generic_to_shared(dst);
    int sz = pred ? 16 : 0;
    asm volatile("cp.async.cg.shared.global [%0], [%1], 16, %2;\n"
                 :: "r"(sdst), "l"(src), "r"(sz));
}
__device__ __forceinline__ void cpa_commit() { asm volatile("cp.async.commit_group;\n"); }
template <int N> __device__ __forceinline__ void cpa_wait() {
    asm volatile("cp.async.wait_group %0;\n" :: "n"(N));
}
__device__ __forceinline__ void sts128(__half* dst, unsigned x, unsigned y,
                                       unsigned z, unsigned w) {
    unsigned s = (unsigned)__cvta_generic_to_shared(dst);
    asm volatile("st.shared.v4.b32 [%0], {%1,%2,%3,%4};"
                 :: "r"(s), "r"(x), "r"(y), "r"(z), "r"(w) : "memory");
}
__device__ __forceinline__ void sts64(__half* dst, unsigned x, unsigned y) {
    unsigned s = (unsigned)__cvta_generic_to_shared(dst);
    asm volatile("st.shared.v2.b32 [%0], {%1,%2};"
                 :: "r"(s), "r"(x), "r"(y) : "memory");
}

// ---------------------------------------------------------------------------
// Kernel 1: xw = x @ theta (fp32), stored transposed as fp16 hi/lo rows.
// ---------------------------------------------------------------------------
__global__ __launch_bounds__(128) void k_xw(const float* __restrict__ x,
                                            const float* __restrict__ theta) {
    __shared__ float a_s[32][33];
    __shared__ float b_s[32][64];
    const int tid = threadIdx.x, rg = tid >> 3, cg = tid & 7;
    const int n0 = blockIdx.x * 32;
    float acc[2][8];
#pragma unroll
    for (int i = 0; i < 2; i++)
#pragma unroll
        for (int j = 0; j < 8; j++) acc[i][j] = 0.f;
    for (int k0 = 0; k0 < IC; k0 += 32) {
#pragma unroll
        for (int t = 0; t < 8; t++) {
            int idx = tid + t * 128, i = idx >> 5, j = idx & 31;
            a_s[j][i] = x[(n0 + i) * IC + k0 + j];
        }
#pragma unroll
        for (int t = 0; t < 4; t++) {
            int idx4 = tid + t * 128, r = idx4 >> 4, c4 = idx4 & 15;
            ((float4*)b_s[r])[c4] = ((const float4*)(theta + (k0 + r) * OC))[c4];
        }
        __syncthreads();
#pragma unroll
        for (int k = 0; k < 32; k++) {
            float a0 = a_s[k][rg * 2], a1 = a_s[k][rg * 2 + 1];
            float4 b0 = *(float4*)&b_s[k][cg * 8], b1 = *(float4*)&b_s[k][cg * 8 + 4];
            float bb[8] = {b0.x, b0.y, b0.z, b0.w, b1.x, b1.y, b1.z, b1.w};
#pragma unroll
            for (int j = 0; j < 8; j++) { acc[0][j] += a0 * bb[j]; acc[1][j] += a1 * bb[j]; }
        }
        __syncthreads();
    }
#pragma unroll
    for (int i = 0; i < 2; i++) {
        int n = n0 + rg * 2 + i;
#pragma unroll
        for (int j = 0; j < 8; j++) {
            int c = cg * 8 + j;
            float v = acc[i][j];
            __half hi = __float2half_rn(v);
            __half lo = __float2half_rn(v - __half2float(hi));
            g_xwT[c * NN + n] = hi;
            g_xwT[(c + 64) * NN + n] = lo;
        }
    }
}

// ---------------------------------------------------------------------------
// Pass 1: P[r][e] = sum_{n in chunk} xwT_stack[r][n] * H[n][e]
//   A[128r][32n] fp16 via cp.async; B[32n][64e] fp16 = H natural via
//   LDG + cvt + STS.64 (conflict-free). Fragments: A ldmatrix, B ldmatrix.trans.
//   de exact fp32 from LDG regs.
// Tile M=128 x N(e)=64 x BK=32. 256 thr / 8 warps (4M x 2N). Grid (157, 12).
// ---------------------------------------------------------------------------
__global__ __launch_bounds__(256) void k_edge_h(const float* __restrict__ H) {
    extern __shared__ char smc[];
    __half* Ah = (__half*)smc;                         // [2][128*ASTR]
    __half* Bs = (__half*)(smc + 2 * 128 * ASTR * 2);  // [2][32*BSTR]
    float*  stg = (float*)Bs;                          // reuse after mainloop

    const int tid = threadIdx.x;
    const int lane = tid & 31, w = tid >> 5;
    const int g = lane >> 2, q = lane & 3;
    const int wm = w & 3, wn = w >> 2;
    const int e0 = blockIdx.x * 64;
    const int sp = blockIdx.y;
    const int kbeg = sp * CHUNK1;
    const int kend = (kbeg + CHUNK1 < NN) ? (kbeg + CHUNK1) : NN;
    const int nk = (kend - kbeg) >> 5;   // chunks are 32-divisible

    // A cp.async: 512 granules of 16B, 2 per thread
    const int ar = tid >> 1;
    const int ag = (tid & 1) * 2;
    // B loader: 16 e-blocks x 16 n; rows npart, npart+16
    const int t15 = tid & 15;
    const int npart = tid >> 4;          // 0..15
    const int e4 = t15 * 4;
    const bool eok = (e0 + e4) < NE;     // NE % 4 == 0

    // ldmatrix offsets (in halves)
    const int aoff = (wm * 32 + (lane & 15)) * ASTR + ((lane >> 4) & 1) * 8;
    const int boff = (((lane >> 3) & 1) * 8 + (lane & 7)) * BSTR
                     + wn * 32 + ((lane >> 4) & 1) * 8;

    float acc[2][4][4];
#pragma unroll
    for (int s2 = 0; s2 < 2; s2++)
#pragma unroll
        for (int nt = 0; nt < 4; nt++)
#pragma unroll
            for (int r = 0; r < 4; r++) acc[s2][nt][r] = 0.f;
    float dep[4] = {0.f, 0.f, 0.f, 0.f};
    float4 h0v, h1v;

    auto cpaA = [&](int buf, int k0) {
        __half* base = Ah + buf * 128 * ASTR + ar * ASTR;
        const __half* src = g_xwT + (long)ar * NN + k0;
#pragma unroll
        for (int j = 0; j < 2; j++)
            cpa16(base + (ag + j) * 8, src + (ag + j) * 8, true);
    };
    auto ldgB = [&](int k0) {
        h0v = eok ? *(const float4*)(H + (long)(k0 + npart) * NE + e0 + e4)
                  : make_float4(0.f, 0.f, 0.f, 0.f);
        h1v = eok ? *(const float4*)(H + (long)(k0 + npart + 16) * NE + e0 + e4)
                  : make_float4(0.f, 0.f, 0.f, 0.f);
    };
    auto stsB = [&](int buf) {
        __half* base = Bs + buf * 32 * BSTR;
        dep[0] += h0v.x + h1v.x;
        dep[1] += h0v.y + h1v.y;
        dep[2] += h0v.z + h1v.z;
        dep[3] += h0v.w + h1v.w;
        sts64(base + npart * BSTR + e4, h2u(h0v.x, h0v.y), h2u(h0v.z, h0v.w));
        sts64(base + (npart + 16) * BSTR + e4, h2u(h1v.x, h1v.y), h2u(h1v.z, h1v.w));
    };
    auto compute = [&](int buf) {
        const __half* ah = Ah + buf * 128 * ASTR;
        const __half* bs = Bs + buf * 32 * BSTR;
#pragma unroll
        for (int ks = 0; ks < 2; ks++) {
            unsigned a[2][4], b[2][4];
            ldsm4(a[0], ah + aoff + ks * 16);
            ldsm4(a[1], ah + aoff + 16 * ASTR + ks * 16);
            ldsm4t(b[0], bs + ks * 16 * BSTR + boff);        // nt 0,1
            ldsm4t(b[1], bs + ks * 16 * BSTR + boff + 16);   // nt 2,3
#pragma unroll
            for (int s2 = 0; s2 < 2; s2++) {
                mma16(acc[s2][0], a[s2][0], a[s2][1], a[s2][2], a[s2][3], b[0][0], b[0][1]);
                mma16(acc[s2][1], a[s2][0], a[s2][1], a[s2][2], a[s2][3], b[0][2], b[0][3]);
                mma16(acc[s2][2], a[s2][0], a[s2][1], a[s2][2], a[s2][3], b[1][0], b[1][1]);
                mma16(acc[s2][3], a[s2][0], a[s2][1], a[s2][2], a[s2][3], b[1][2], b[1][3]);
            }
        }
    };

    // prolog
    ldgB(kbeg);
    cpaA(0, kbeg); cpa_commit();
    stsB(0);
    cpa_wait<0>(); __syncthreads();

    for (int it = 0; it < nk; it++) {
        const int buf = it & 1, nxt = buf ^ 1;
        const bool more = (it + 1 < nk);
        if (more) {
            int k1 = kbeg + (it + 1) * 32;
            ldgB(k1);
            cpaA(nxt, k1); cpa_commit();
        }
        compute(buf);
        if (more) {
            stsB(nxt);
            cpa_wait<0>(); __syncthreads();
        }
    }
    __syncthreads();

    // de reduction via staging (Bs dead): thread held e = e0 + t15*4 + c
#pragma unroll
    for (int c = 0; c < 4; c++) stg[tid * 4 + c] = dep[c];
    __syncthreads();
    if (tid < 64) {
        float v = 0.f;
#pragma unroll
        for (int np = 0; np < 16; np++)
            v += stg[(np * 16 + (tid >> 2)) * 4 + (tid & 3)];
        int e = e0 + tid;
        if (e < NE) g_de_part[sp * NE + e] = v;
    }

    // store raw fp32 partials [sp][row r][e]
    float* op = g_p1 + (long)sp * 128 * NEP1;
#pragma unroll
    for (int s2 = 0; s2 < 2; s2++) {
        int r0 = wm * 32 + s2 * 16 + g;
#pragma unroll
        for (int nt = 0; nt < 4; nt++) {
            int e = e0 + wn * 32 + nt * 8 + 2 * q;
            *(float2*)&op[(long)r0 * NEP1 + e] = make_float2(acc[s2][nt][0], acc[s2][nt][1]);
            *(float2*)&op[(long)(r0 + 8) * NEP1 + e] = make_float2(acc[s2][nt][2], acc[s2][nt][3]);
        }
    }
}

// Finalize 1: efT[c][e] = fp16((sum_sp(hi+lo)) / sum_sp de); zero-pad e>=NE.
__global__ __launch_bounds__(256) void k_fin1() {
    int e = blockIdx.x * 256 + threadIdx.x;
    int c = blockIdx.y;
    if (e >= NEP2) return;
    if (e >= NE) { g_efT[c * NEP2 + e] = __ushort_as_half(0); return; }
    float s = 0.f, d = 0.f;
#pragma unroll
    for (int sp = 0; sp < SPLIT1; sp++) {
        s += g_p1[((long)sp * 128 + c) * NEP1 + e];
        s += g_p1[((long)sp * 128 + c + 64) * NEP1 + e];
        d += g_de_part[sp * NE + e];
    }
    g_efT[c * NEP2 + e] = __float2half_rn(s / d);
}

// ---------------------------------------------------------------------------
// Pass 2: out[n][c] += sum_{e in chunk} H[n][e] * efT[c][e]
//   A[128n][32e] fp16 = H via LDG+cvt+STS.128 (dn exact from LDG regs)
//   B[64c][32e] fp16 = g_efT via cp.async. Fragments via ldmatrix (non-trans).
// Tile M=128 x N=64 x BK=32. 256 thr / 8 warps (4M x 2N). Grid (157, 8).
// ---------------------------------------------------------------------------
__global__ __launch_bounds__(256) void k_node_h(const float* __restrict__ H) {
    extern __shared__ char smc[];
    __half* As = (__half*)smc;                         // [2][128*ASTR]
    __half* Bs = (__half*)(smc + 2 * 128 * ASTR * 2);  // [2][64*ASTR]
    __shared__ float sred[256];

    const int tid = threadIdx.x;
    const int lane = tid & 31, w = tid >> 5;
    const int g = lane >> 2, q = lane & 3;
    const int wm = w & 3, wn = w >> 2;
    const int n0 = blockIdx.x * 128;
    const int sp = blockIdx.y;
    const int kbeg = sp * CHUNK2;
    const int kend = (kbeg + CHUNK2 < NE) ? (kbeg + CHUNK2) : NE;
    const int nk = (kend - kbeg + 31) >> 5;

    const int  arow   = tid >> 1;
    const bool row_ok = (n0 + arow) < NN;
    const long aoff_g = (long)(n0 + arow) * NE;
    const int  akb    = (tid & 1) * 16;   // k-half base (halves)
    const int  brow   = tid >> 2;         // B row (c) 0..63
    const int  bg     = tid & 3;          // 16B granule

    // ldmatrix offsets (halves)
    const int aoff = (wm * 32 + (lane & 15)) * ASTR + ((lane >> 4) & 1) * 8;
    const int boff = (wn * 32 + ((lane >> 4) & 1) * 8 + (lane & 7)) * ASTR
                     + ((lane >> 3) & 1) * 8;

    float acc[2][4][4];
#pragma unroll
    for (int s2 = 0; s2 < 2; s2++)
#pragma unroll
        for (int nt = 0; nt < 4; nt++)
#pragma unroll
            for (int r = 0; r < 4; r++) acc[s2][nt][r] = 0.f;
    float dn_acc = 0.f;
    float4 areg[4];

    auto ldgA = [&](int k0) {
#pragma unroll
        for (int j = 0; j < 4; j++) {
            int kf = akb + 4 * j;
            areg[j] = (row_ok && (k0 + kf + 4 <= NE))
                          ? *(const float4*)(H + aoff_g + k0 + kf)
                          : make_float4(0.f, 0.f, 0.f, 0.f);
        }
    };
    auto stsA = [&](int buf) {
        __half* dst = As + buf * 128 * ASTR + arow * ASTR + akb;
        unsigned u[8];
#pragma unroll
        for (int j = 0; j < 4; j++) {
            dn_acc += (areg[j].x + areg[j].y) + (areg[j].z + areg[j].w);
            u[2 * j]     = h2u(areg[j].x, areg[j].y);
            u[2 * j + 1] = h2u(areg[j].z, areg[j].w);
        }
        sts128(dst, u[0], u[1], u[2], u[3]);
        sts128(dst + 8, u[4], u[5], u[6], u[7]);
    };
    auto cpaB = [&](int buf, int k0) {
        cpa16(Bs + buf * 64 * ASTR + brow * ASTR + bg * 8,
              g_efT + (long)brow * NEP2 + k0 + bg * 8, true);
    };
    auto compute = [&](int buf) {
        const __half* as = As + buf * 128 * ASTR;
        const __half* bs = Bs + buf * 64 * ASTR;
#pragma unroll
        for (int ks = 0; ks < 2; ks++) {
            unsigned a[2][4], b[2][4];
            ldsm4(a[0], as + aoff + ks * 16);
            ldsm4(a[1], as + aoff + 16 * ASTR + ks * 16);
            ldsm4(b[0], bs + boff + ks * 16);                 // nt 0,1
            ldsm4(b[1], bs + boff + 16 * ASTR + ks * 16);     // nt 2,3
#pragma unroll
            for (int s2 = 0; s2 < 2; s2++) {
                mma16(acc[s2][0], a[s2][0], a[s2][1], a[s2][2], a[s2][3], b[0][0], b[0][1]);
                mma16(acc[s2][1], a[s2][0], a[s2][1], a[s2][2], a[s2][3], b[0][2], b[0][3]);
                mma16(acc[s2][2], a[s2][0], a[s2][1], a[s2][2], a[s2][3], b[1][0], b[1][1]);
                mma16(acc[s2][3], a[s2][0], a[s2][1], a[s2][2], a[s2][3], b[1][2], b[1][3]);
            }
        }
    };

    // prolog
    ldgA(kbeg);
    cpaB(0, kbeg); cpa_commit();
    stsA(0);
    cpa_wait<0>(); __syncthreads();

    for (int it = 0; it < nk; it++) {
        const int buf = it & 1, nxt = buf ^ 1;
        const bool more = (it + 1 < nk);
        if (more) {
            int k1 = kbeg + (it + 1) * 32;
            ldgA(k1);
            cpaB(nxt, k1); cpa_commit();
        }
        compute(buf);
        if (more) {
            stsA(nxt);
            cpa_wait<0>(); __syncthreads();
        }
    }

    sred[tid] = dn_acc;
    __syncthreads();
    if (tid < 128) {
        int n = n0 + tid;
        if (n < NN) g_dn_part[sp * NN + n] = sred[2 * tid] + sred[2 * tid + 1];
    }

    float* op = g_out_part + (long)sp * NN * OC;
#pragma unroll
    for (int s2 = 0; s2 < 2; s2++) {
        int nA = n0 + wm * 32 + s2 * 16 + g;
        int nB = nA + 8;
#pragma unroll
        for (int nt = 0; nt < 4; nt++) {
            int c = wn * 32 + nt * 8 + 2 * q;
            if (nA < NN)
                *(float2*)&op[(long)nA * OC + c] = make_float2(acc[s2][nt][0], acc[s2][nt][1]);
            if (nB < NN)
                *(float2*)&op[(long)nB * OC + c] = make_float2(acc[s2][nt][2], acc[s2][nt][3]);
        }
    }
}

// Finalize 2: out = (sum_sp part) / (sum_sp dn)
__global__ __launch_bounds__(256) void k_fin2(float* __restrict__ out) {
    int idx = blockIdx.x * 256 + threadIdx.x;
    int n = idx >> 6;
    float s = 0.f, d = 0.f;
#pragma unroll
    for (int sp = 0; sp < SPLIT2; sp++) {
        s += g_out_part[(long)sp * NN * OC + idx];
        d += g_dn_part[sp * NN + n];
    }
    out[idx] = s / d;
}

// ---------------------------------------------------------------------------
extern "C" void kernel_launch(void* const* d_in, const int* in_sizes, int n_in,
                              void* d_out, int out_size) {
    const float* x     = (const float*)d_in[0];   // [20000, 128]
    const float* H     = (const float*)d_in[1];   // [20000, 10000]
    const float* theta = (const float*)d_in[2];   // [128, 64]
    float* out         = (float*)d_out;           // [20000, 64]

    const int smem1 = 2 * 128 * ASTR * 2 + 2 * 32 * BSTR * 2;   // 29696 B
    const int smem2 = 2 * 128 * ASTR * 2 + 2 * 64 * ASTR * 2;   // 30720 B

    k_xw<<<NN / 32, 128>>>(x, theta);
    k_edge_h<<<dim3(157, SPLIT1), 256, smem1>>>(H);
    k_fin1<<<dim3(NEP2 / 256, OC), 256>>>();
    k_node_h<<<dim3(157, SPLIT2), 256, smem2>>>(H);
    k_fin2<<<(NN * OC) / 256, 256>>>(out);
    (void)in_sizes; (void)n_in; (void)out_size;
}

// round 17
// speedup vs baseline: 1.6392x; 1.0900x over previous
#include <cuda_runtime.h>
#include <cuda_fp16.h>
#include <cstdint>

#define NN 20000
#define NE 10000
#define IC 128
#define OC 64
#define SPLIT1 12
#define SPLIT2 8
#define CHUNK1 1696    // pass-1 n-chunk: 53 k-tiles of 32 (last split: 42)
#define CHUNK2 1280    // pass-2 e-chunk: 40 k-tiles (last split: 33)
#define NEP1 10048     // 157*64: pass-1 partial stride / g_Hh column stride
#define NEP2 10240     // pass-2 padded efT stride (halves)
#define ASTR 40        // smem stride for 32-half rows (pad 8)
#define BSTR 72        // pass-1 B smem stride for 64-half rows (pad 8)

// Scratch (device globals — no allocation in kernel_launch).
__device__ __half g_xwT[128 * NN];          // rows 0-63: hi(xw)^T, 64-127: lo
__device__ __half g_Hh[(size_t)NN * NEP1];  // fp16 H [n][e], e>=NE zero-padded
__device__ __half g_efT[OC * NEP2];         // fp16 edge features [c][e], zero-padded
__device__ float  g_p1[SPLIT1 * 128 * NEP1];
__device__ float  g_de_part[SPLIT1 * NE];
__device__ float  g_out_part[SPLIT2 * NN * OC];
__device__ float  g_dn_part[SPLIT2 * NN];

// ---------------- helpers ----------------
__device__ __forceinline__ unsigned h2u(float lo, float hi) {
    __half2 h = __floats2half2_rn(lo, hi);
    return *(unsigned*)&h;
}
__device__ __forceinline__ void mma16(float* c, unsigned a0, unsigned a1,
                                      unsigned a2, unsigned a3,
                                      unsigned b0, unsigned b1) {
    asm volatile(
        "mma.sync.aligned.m16n8k16.row.col.f32.f16.f16.f32 "
        "{%0,%1,%2,%3}, {%4,%5,%6,%7}, {%8,%9}, {%0,%1,%2,%3};\n"
        : "+f"(c[0]), "+f"(c[1]), "+f"(c[2]), "+f"(c[3])
        : "r"(a0), "r"(a1), "r"(a2), "r"(a3), "r"(b0), "r"(b1));
}
__device__ __forceinline__ void ldsm4(unsigned* r, const __half* p) {
    unsigned a = (unsigned)__cvta_generic_to_shared(p);
    asm volatile("ldmatrix.sync.aligned.m8n8.x4.shared.b16 {%0,%1,%2,%3}, [%4];"
                 : "=r"(r[0]), "=r"(r[1]), "=r"(r[2]), "=r"(r[3]) : "r"(a));
}
__device__ __forceinline__ void ldsm4t(unsigned* r, const __half* p) {
    unsigned a = (unsigned)__cvta_generic_to_shared(p);
    asm volatile("ldmatrix.sync.aligned.m8n8.x4.trans.shared.b16 {%0,%1,%2,%3}, [%4];"
                 : "=r"(r[0]), "=r"(r[1]), "=r"(r[2]), "=r"(r[3]) : "r"(a));
}
__device__ __forceinline__ void cpa16(void* dst, const void* src, bool pred) {
    unsigned sdst = (unsigned)__cvta_generic_to_shared(dst);
    int sz = pred ? 16 : 0;
    asm volatile("cp.async.cg.shared.global [%0], [%1], 16, %2;\n"
                 :: "r"(sdst), "l"(src), "r"(sz));
}
__device__ __forceinline__ void cpa_commit() { asm volatile("cp.async.commit_group;\n"); }
template <int N> __device__ __forceinline__ void cpa_wait() {
    asm volatile("cp.async.wait_group %0;\n" :: "n"(N));
}
__device__ __forceinline__ void sts64(__half* dst, unsigned x, unsigned y) {
    unsigned s = (unsigned)__cvta_generic_to_shared(dst);
    asm volatile("st.shared.v2.b32 [%0], {%1,%2};"
                 :: "r"(s), "r"(x), "r"(y) : "memory");
}

// ---------------------------------------------------------------------------
// Kernel 1: xw = x @ theta (fp32), stored transposed as fp16 hi/lo rows.
// ---------------------------------------------------------------------------
__global__ __launch_bounds__(128) void k_xw(const float* __restrict__ x,
                                            const float* __restrict__ theta) {
    __shared__ float a_s[32][33];
    __shared__ float b_s[32][64];
    const int tid = threadIdx.x, rg = tid >> 3, cg = tid & 7;
    const int n0 = blockIdx.x * 32;
    float acc[2][8];
#pragma unroll
    for (int i = 0; i < 2; i++)
#pragma unroll
        for (int j = 0; j < 8; j++) acc[i][j] = 0.f;
    for (int k0 = 0; k0 < IC; k0 += 32) {
#pragma unroll
        for (int t = 0; t < 8; t++) {
            int idx = tid + t * 128, i = idx >> 5, j = idx & 31;
            a_s[j][i] = x[(n0 + i) * IC + k0 + j];
        }
#pragma unroll
        for (int t = 0; t < 4; t++) {
            int idx4 = tid + t * 128, r = idx4 >> 4, c4 = idx4 & 15;
            ((float4*)b_s[r])[c4] = ((const float4*)(theta + (k0 + r) * OC))[c4];
        }
        __syncthreads();
#pragma unroll
        for (int k = 0; k < 32; k++) {
            float a0 = a_s[k][rg * 2], a1 = a_s[k][rg * 2 + 1];
            float4 b0 = *(float4*)&b_s[k][cg * 8], b1 = *(float4*)&b_s[k][cg * 8 + 4];
            float bb[8] = {b0.x, b0.y, b0.z, b0.w, b1.x, b1.y, b1.z, b1.w};
#pragma unroll
            for (int j = 0; j < 8; j++) { acc[0][j] += a0 * bb[j]; acc[1][j] += a1 * bb[j]; }
        }
        __syncthreads();
    }
#pragma unroll
    for (int i = 0; i < 2; i++) {
        int n = n0 + rg * 2 + i;
#pragma unroll
        for (int j = 0; j < 8; j++) {
            int c = cg * 8 + j;
            float v = acc[i][j];
            __half hi = __float2half_rn(v);
            __half lo = __float2half_rn(v - __half2float(hi));
            g_xwT[c * NN + n] = hi;
            g_xwT[(c + 64) * NN + n] = lo;
        }
    }
}

// ---------------------------------------------------------------------------
// Pass 1: P[r][e] = sum_{n in chunk} xwT_stack[r][n] * H[n][e]
//   A[128r][32n] fp16 via cp.async; B[32n][64e] fp16 = H natural via
//   LDG + cvt + STS.64. Also materializes fp16 H into g_Hh (each element of H
//   is owned by exactly one CTA). de exact fp32 from LDG regs.
// Tile M=128 x N(e)=64 x BK=32. 256 thr / 8 warps (4M x 2N). Grid (157, 12).
// ---------------------------------------------------------------------------
__global__ __launch_bounds__(256) void k_edge_h(const float* __restrict__ H) {
    extern __shared__ char smc[];
    __half* Ah = (__half*)smc;                         // [2][128*ASTR]
    __half* Bs = (__half*)(smc + 2 * 128 * ASTR * 2);  // [2][32*BSTR]
    float*  stg = (float*)Bs;                          // reuse after mainloop

    const int tid = threadIdx.x;
    const int lane = tid & 31, w = tid >> 5;
    const int g = lane >> 2, q = lane & 3;
    const int wm = w & 3, wn = w >> 2;
    const int e0 = blockIdx.x * 64;
    const int sp = blockIdx.y;
    const int kbeg = sp * CHUNK1;
    const int kend = (kbeg + CHUNK1 < NN) ? (kbeg + CHUNK1) : NN;
    const int nk = (kend - kbeg) >> 5;   // chunks are 32-divisible

    const int ar = tid >> 1;
    const int ag = (tid & 1) * 2;
    const int t15 = tid & 15;
    const int npart = tid >> 4;          // 0..15
    const int e4 = t15 * 4;
    const bool eok = (e0 + e4) < NE;     // NE % 4 == 0

    const int aoff = (wm * 32 + (lane & 15)) * ASTR + ((lane >> 4) & 1) * 8;
    const int boff = (((lane >> 3) & 1) * 8 + (lane & 7)) * BSTR
                     + wn * 32 + ((lane >> 4) & 1) * 8;

    float acc[2][4][4];
#pragma unroll
    for (int s2 = 0; s2 < 2; s2++)
#pragma unroll
        for (int nt = 0; nt < 4; nt++)
#pragma unroll
            for (int r = 0; r < 4; r++) acc[s2][nt][r] = 0.f;
    float dep[4] = {0.f, 0.f, 0.f, 0.f};
    float4 h0v, h1v;

    auto cpaA = [&](int buf, int k0) {
        __half* base = Ah + buf * 128 * ASTR + ar * ASTR;
        const __half* src = g_xwT + (long)ar * NN + k0;
#pragma unroll
        for (int j = 0; j < 2; j++)
            cpa16(base + (ag + j) * 8, src + (ag + j) * 8, true);
    };
    auto ldgB = [&](int k0) {
        h0v = eok ? *(const float4*)(H + (long)(k0 + npart) * NE + e0 + e4)
                  : make_float4(0.f, 0.f, 0.f, 0.f);
        h1v = eok ? *(const float4*)(H + (long)(k0 + npart + 16) * NE + e0 + e4)
                  : make_float4(0.f, 0.f, 0.f, 0.f);
    };
    auto stsB = [&](int buf, int k0) {
        __half* base = Bs + buf * 32 * BSTR;
        dep[0] += h0v.x + h1v.x;
        dep[1] += h0v.y + h1v.y;
        dep[2] += h0v.z + h1v.z;
        dep[3] += h0v.w + h1v.w;
        unsigned p00 = h2u(h0v.x, h0v.y), p01 = h2u(h0v.z, h0v.w);
        unsigned p10 = h2u(h1v.x, h1v.y), p11 = h2u(h1v.z, h1v.w);
        sts64(base + npart * BSTR + e4, p00, p01);
        sts64(base + (npart + 16) * BSTR + e4, p10, p11);
        // materialize fp16 H (zero-padded at e>=NE)
        size_t gb = (size_t)(k0 + npart) * NEP1 + e0 + e4;
        *(uint2*)(g_Hh + gb) = make_uint2(p00, p01);
        *(uint2*)(g_Hh + gb + (size_t)16 * NEP1) = make_uint2(p10, p11);
    };
    auto compute = [&](int buf) {
        const __half* ah = Ah + buf * 128 * ASTR;
        const __half* bs = Bs + buf * 32 * BSTR;
#pragma unroll
        for (int ks = 0; ks < 2; ks++) {
            unsigned a[2][4], b[2][4];
            ldsm4(a[0], ah + aoff + ks * 16);
            ldsm4(a[1], ah + aoff + 16 * ASTR + ks * 16);
            ldsm4t(b[0], bs + ks * 16 * BSTR + boff);
            ldsm4t(b[1], bs + ks * 16 * BSTR + boff + 16);
#pragma unroll
            for (int s2 = 0; s2 < 2; s2++) {
                mma16(acc[s2][0], a[s2][0], a[s2][1], a[s2][2], a[s2][3], b[0][0], b[0][1]);
                mma16(acc[s2][1], a[s2][0], a[s2][1], a[s2][2], a[s2][3], b[0][2], b[0][3]);
                mma16(acc[s2][2], a[s2][0], a[s2][1], a[s2][2], a[s2][3], b[1][0], b[1][1]);
                mma16(acc[s2][3], a[s2][0], a[s2][1], a[s2][2], a[s2][3], b[1][2], b[1][3]);
            }
        }
    };

    // prolog
    ldgB(kbeg);
    cpaA(0, kbeg); cpa_commit();
    stsB(0, kbeg);
    cpa_wait<0>(); __syncthreads();

    for (int it = 0; it < nk; it++) {
        const int buf = it & 1, nxt = buf ^ 1;
        const bool more = (it + 1 < nk);
        if (more) {
            int k1 = kbeg + (it + 1) * 32;
            ldgB(k1);
            cpaA(nxt, k1); cpa_commit();
        }
        compute(buf);
        if (more) {
            stsB(nxt, kbeg + (it + 1) * 32);
            cpa_wait<0>(); __syncthreads();
        }
    }
    __syncthreads();

    // de reduction via staging (Bs dead): thread held e = e0 + t15*4 + c
#pragma unroll
    for (int c = 0; c < 4; c++) stg[tid * 4 + c] = dep[c];
    __syncthreads();
    if (tid < 64) {
        float v = 0.f;
#pragma unroll
        for (int np = 0; np < 16; np++)
            v += stg[(np * 16 + (tid >> 2)) * 4 + (tid & 3)];
        int e = e0 + tid;
        if (e < NE) g_de_part[sp * NE + e] = v;
    }

    // store raw fp32 partials [sp][row r][e]
    float* op = g_p1 + (long)sp * 128 * NEP1;
#pragma unroll
    for (int s2 = 0; s2 < 2; s2++) {
        int r0 = wm * 32 + s2 * 16 + g;
#pragma unroll
        for (int nt = 0; nt < 4; nt++) {
            int e = e0 + wn * 32 + nt * 8 + 2 * q;
            *(float2*)&op[(long)r0 * NEP1 + e] = make_float2(acc[s2][nt][0], acc[s2][nt][1]);
            *(float2*)&op[(long)(r0 + 8) * NEP1 + e] = make_float2(acc[s2][nt][2], acc[s2][nt][3]);
        }
    }
}

// Finalize 1: efT[c][e] = fp16((sum_sp(hi+lo)) / sum_sp de); zero-pad e>=NE.
__global__ __launch_bounds__(256) void k_fin1() {
    int e = blockIdx.x * 256 + threadIdx.x;
    int c = blockIdx.y;
    if (e >= NEP2) return;
    if (e >= NE) { g_efT[c * NEP2 + e] = __ushort_as_half(0); return; }
    float s = 0.f, d = 0.f;
#pragma unroll
    for (int sp = 0; sp < SPLIT1; sp++) {
        s += g_p1[((long)sp * 128 + c) * NEP1 + e];
        s += g_p1[((long)sp * 128 + c + 64) * NEP1 + e];
        d += g_de_part[sp * NE + e];
    }
    g_efT[c * NEP2 + e] = __float2half_rn(s / d);
}

// ---------------------------------------------------------------------------
// Pass 2: out[n][c] += sum_{e in chunk} H[n][e] * efT[c][e]
//   A[128n][32e] fp16 = g_Hh via pure cp.async (no LDG/CVT/STS).
//   B[64c][32e] fp16 = g_efT via cp.async. Fragments via ldmatrix.
//   dn accumulated fp32 from the fp16 A tile in smem (2 LDS.128/thread/tile).
// Tile M=128 x N=64 x BK=32. 256 thr / 8 warps (4M x 2N). Grid (157, 8).
// ---------------------------------------------------------------------------
__global__ __launch_bounds__(256) void k_node_h() {
    extern __shared__ char smc[];
    __half* As = (__half*)smc;                         // [2][128*ASTR]
    __half* Bs = (__half*)(smc + 2 * 128 * ASTR * 2);  // [2][64*ASTR]
    __shared__ float sred[256];

    const int tid = threadIdx.x;
    const int lane = tid & 31, w = tid >> 5;
    const int g = lane >> 2, q = lane & 3;
    const int wm = w & 3, wn = w >> 2;
    const int n0 = blockIdx.x * 128;
    const int sp = blockIdx.y;
    const int kbeg = sp * CHUNK2;
    const int kend = (kbeg + CHUNK2 < NE) ? (kbeg + CHUNK2) : NE;
    const int nk = (kend - kbeg + 31) >> 5;

    const int  ar     = tid >> 1;           // A row 0..127
    const int  ah8    = (tid & 1) * 16;     // half offset base within row
    const bool row_ok = (n0 + ar) < NN;
    const int  brow   = tid >> 2;           // B row (c) 0..63
    const int  bg     = tid & 3;            // 16B granule

    const int aoff = (wm * 32 + (lane & 15)) * ASTR + ((lane >> 4) & 1) * 8;
    const int boff = (wn * 32 + ((lane >> 4) & 1) * 8 + (lane & 7)) * ASTR
                     + ((lane >> 3) & 1) * 8;

    float acc[2][4][4];
#pragma unroll
    for (int s2 = 0; s2 < 2; s2++)
#pragma unroll
        for (int nt = 0; nt < 4; nt++)
#pragma unroll
            for (int r = 0; r < 4; r++) acc[s2][nt][r] = 0.f;
    float dn_acc = 0.f;

    auto cpaA = [&](int buf, int k0) {
        __half* dst = As + buf * 128 * ASTR + ar * ASTR + ah8;
        const __half* src = g_Hh + (size_t)(n0 + ar) * NEP1 + k0 + ah8;
        cpa16(dst, src, row_ok);
        cpa16(dst + 8, src + 8, row_ok);
    };
    auto cpaB = [&](int buf, int k0) {
        cpa16(Bs + buf * 64 * ASTR + brow * ASTR + bg * 8,
              g_efT + (long)brow * NEP2 + k0 + bg * 8, true);
    };
    auto dnadd = [&](int buf) {
        const uint4* p = (const uint4*)(As + buf * 128 * ASTR + ar * ASTR + ah8);
        uint4 v0 = p[0], v1 = p[1];
        unsigned u[8] = {v0.x, v0.y, v0.z, v0.w, v1.x, v1.y, v1.z, v1.w};
#pragma unroll
        for (int i = 0; i < 8; i++) {
            float2 f = __half22float2(*(__half2*)&u[i]);
            dn_acc += f.x + f.y;
        }
    };
    auto compute = [&](int buf) {
        const __half* as = As + buf * 128 * ASTR;
        const __half* bs = Bs + buf * 64 * ASTR;
#pragma unroll
        for (int ks = 0; ks < 2; ks++) {
            unsigned a[2][4], b[2][4];
            ldsm4(a[0], as + aoff + ks * 16);
            ldsm4(a[1], as + aoff + 16 * ASTR + ks * 16);
            ldsm4(b[0], bs + boff + ks * 16);
            ldsm4(b[1], bs + boff + 16 * ASTR + ks * 16);
#pragma unroll
            for (int s2 = 0; s2 < 2; s2++) {
                mma16(acc[s2][0], a[s2][0], a[s2][1], a[s2][2], a[s2][3], b[0][0], b[0][1]);
                mma16(acc[s2][1], a[s2][0], a[s2][1], a[s2][2], a[s2][3], b[0][2], b[0][3]);
                mma16(acc[s2][2], a[s2][0], a[s2][1], a[s2][2], a[s2][3], b[1][0], b[1][1]);
                mma16(acc[s2][3], a[s2][0], a[s2][1], a[s2][2], a[s2][3], b[1][2], b[1][3]);
            }
        }
    };

    // prolog
    cpaA(0, kbeg); cpaB(0, kbeg); cpa_commit();
    cpa_wait<0>(); __syncthreads();

    for (int it = 0; it < nk; it++) {
        const int buf = it & 1, nxt = buf ^ 1;
        const bool more = (it + 1 < nk);
        if (more) {
            int k1 = kbeg + (it + 1) * 32;
            cpaA(nxt, k1); cpaB(nxt, k1); cpa_commit();
        }
        dnadd(buf);
        compute(buf);
        if (more) {
            cpa_wait<0>(); __syncthreads();
        }
    }

    sred[tid] = dn_acc;
    __syncthreads();
    if (tid < 128) {
        int n = n0 + tid;
        if (n < NN) g_dn_part[sp * NN + n] = sred[2 * tid] + sred[2 * tid + 1];
    }

    float* op = g_out_part + (long)sp * NN * OC;
#pragma unroll
    for (int s2 = 0; s2 < 2; s2++) {
        int nA = n0 + wm * 32 + s2 * 16 + g;
        int nB = nA + 8;
#pragma unroll
        for (int nt = 0; nt < 4; nt++) {
            int c = wn * 32 + nt * 8 + 2 * q;
            if (nA < NN)
                *(float2*)&op[(long)nA * OC + c] = make_float2(acc[s2][nt][0], acc[s2][nt][1]);
            if (nB < NN)
                *(float2*)&op[(long)nB * OC + c] = make_float2(acc[s2][nt][2], acc[s2][nt][3]);
        }
    }
}

// Finalize 2: out = (sum_sp part) / (sum_sp dn)
__global__ __launch_bounds__(256) void k_fin2(float* __restrict__ out) {
    int idx = blockIdx.x * 256 + threadIdx.x;
    int n = idx >> 6;
    float s = 0.f, d = 0.f;
#pragma unroll
    for (int sp = 0; sp < SPLIT2; sp++) {
        s += g_out_part[(long)sp * NN * OC + idx];
        d += g_dn_part[sp * NN + n];
    }
    out[idx] = s / d;
}

// ---------------------------------------------------------------------------
extern "C" void kernel_launch(void* const* d_in, const int* in_sizes, int n_in,
                              void* d_out, int out_size) {
    const float* x     = (const float*)d_in[0];   // [20000, 128]
    const float* H     = (const float*)d_in[1];   // [20000, 10000]
    const float* theta = (const float*)d_in[2];   // [128, 64]
    float* out         = (float*)d_out;           // [20000, 64]

    const int smem1 = 2 * 128 * ASTR * 2 + 2 * 32 * BSTR * 2;   // 29696 B
    const int smem2 = 2 * 128 * ASTR * 2 + 2 * 64 * ASTR * 2;   // 30720 B

    k_xw<<<NN / 32, 128>>>(x, theta);
    k_edge_h<<<dim3(157, SPLIT1), 256, smem1>>>(H);
    k_fin1<<<dim3(NEP2 / 256, OC), 256>>>();
    k_node_h<<<dim3(157, SPLIT2), 256, smem2>>>();
    k_fin2<<<(NN * OC) / 256, 256>>>(out);
    (void)in_sizes; (void)n_in; (void)out_size;
}